// round 5
// baseline (speedup 1.0000x reference)
#include <cuda_runtime.h>
#include <math.h>

#define BATCH 16
#define DIMC  512
#define RES   1024
#define NHKD  256
#define HQKV  1536
#define DHDIM 1024
#define NHEAD 8
#define KD    32
#define DV    128
#define ATT_SCALE 0.17677669529663687f

// ---------------- scratch (static device globals; no allocations) -------------
__device__ float g_qkv[BATCH * HQKV * RES];   // 100.7 MB
__device__ float g_q  [BATCH * NHKD * RES];   // 16.8 MB
__device__ float g_att[BATCH * DHDIM * RES];  // 67 MB

// ---------------- GEMM (C[b,o,l] = sum_c W[o,c] * X[b,c,l]) + BN ---------------
// 128x128 tile, BK=8, 128 threads, 16x8 microtile, double-buffered smem.
__global__ __launch_bounds__(128) void gemm_bn_kernel(
    const float* __restrict__ W, const float* __restrict__ X,
    const float* __restrict__ gg, const float* __restrict__ bb,
    const float* __restrict__ mm, const float* __restrict__ vv,
    float* __restrict__ out, int O, int C, int L)
{
    __shared__ float As[2][8][128];
    __shared__ float Bs[2][8][128];

    const int b  = blockIdx.z;
    const float* Xb = X + (size_t)b * C * L;
    float* Ob = out + (size_t)b * O * L;
    const int o0 = blockIdx.y * 128;
    const int l0 = blockIdx.x * 128;
    const int t  = threadIdx.x;
    const int og = t >> 4;
    const int lg = t & 15;

    float acc[16][8];
    #pragma unroll
    for (int i = 0; i < 16; i++)
        #pragma unroll
        for (int j = 0; j < 8; j++) acc[i][j] = 0.0f;

    float4 ra0, ra1, rb0, rb1;
    const int bk0 = t >> 5;
    const int bl4 = (t & 31) * 4;

    {
        const float* wr = &W[(size_t)(o0 + t) * C];
        ra0 = *(const float4*)&wr[0];
        ra1 = *(const float4*)&wr[4];
        rb0 = *(const float4*)&Xb[(size_t)bk0 * L + l0 + bl4];
        rb1 = *(const float4*)&Xb[(size_t)(bk0 + 4) * L + l0 + bl4];
        As[0][0][t] = ra0.x; As[0][1][t] = ra0.y; As[0][2][t] = ra0.z; As[0][3][t] = ra0.w;
        As[0][4][t] = ra1.x; As[0][5][t] = ra1.y; As[0][6][t] = ra1.z; As[0][7][t] = ra1.w;
        *(float4*)&Bs[0][bk0][bl4]     = rb0;
        *(float4*)&Bs[0][bk0 + 4][bl4] = rb1;
    }
    __syncthreads();

    int buf = 0;
    for (int k0 = 0; k0 < C; k0 += 8) {
        const bool more = (k0 + 8 < C);
        if (more) {
            const float* wr = &W[(size_t)(o0 + t) * C + k0 + 8];
            ra0 = *(const float4*)&wr[0];
            ra1 = *(const float4*)&wr[4];
            rb0 = *(const float4*)&Xb[(size_t)(k0 + 8 + bk0) * L + l0 + bl4];
            rb1 = *(const float4*)&Xb[(size_t)(k0 + 12 + bk0) * L + l0 + bl4];
        }
        #pragma unroll
        for (int k = 0; k < 8; k++) {
            float av[16], bv[8];
            *(float4*)&av[0]  = *(const float4*)&As[buf][k][og * 16];
            *(float4*)&av[4]  = *(const float4*)&As[buf][k][og * 16 + 4];
            *(float4*)&av[8]  = *(const float4*)&As[buf][k][og * 16 + 8];
            *(float4*)&av[12] = *(const float4*)&As[buf][k][og * 16 + 12];
            *(float4*)&bv[0]  = *(const float4*)&Bs[buf][k][lg * 4];
            *(float4*)&bv[4]  = *(const float4*)&Bs[buf][k][lg * 4 + 64];
            #pragma unroll
            for (int i = 0; i < 16; i++)
                #pragma unroll
                for (int j = 0; j < 8; j++)
                    acc[i][j] = fmaf(av[i], bv[j], acc[i][j]);
        }
        if (more) {
            int nb = buf ^ 1;
            As[nb][0][t] = ra0.x; As[nb][1][t] = ra0.y; As[nb][2][t] = ra0.z; As[nb][3][t] = ra0.w;
            As[nb][4][t] = ra1.x; As[nb][5][t] = ra1.y; As[nb][6][t] = ra1.z; As[nb][7][t] = ra1.w;
            *(float4*)&Bs[nb][bk0][bl4]     = rb0;
            *(float4*)&Bs[nb][bk0 + 4][bl4] = rb1;
        }
        __syncthreads();
        buf ^= 1;
    }

    #pragma unroll
    for (int i = 0; i < 16; i++) {
        int o = o0 + og * 16 + i;
        float inv  = gg[o] * rsqrtf(vv[o] + 1e-5f);
        float beta = bb[o] - mm[o] * inv;
        float4 r0, r1;
        r0.x = fmaf(acc[i][0], inv, beta); r0.y = fmaf(acc[i][1], inv, beta);
        r0.z = fmaf(acc[i][2], inv, beta); r0.w = fmaf(acc[i][3], inv, beta);
        r1.x = fmaf(acc[i][4], inv, beta); r1.y = fmaf(acc[i][5], inv, beta);
        r1.z = fmaf(acc[i][6], inv, beta); r1.w = fmaf(acc[i][7], inv, beta);
        *(float4*)&Ob[(size_t)o * L + l0 + lg * 4]      = r0;
        *(float4*)&Ob[(size_t)o * L + l0 + 64 + lg * 4] = r1;
    }
}

// ---------------- depthwise conv (k=3, pad=1) + BN on q channels ----------------
__global__ __launch_bounds__(256) void dwconv_bn_kernel(
    const float* __restrict__ qkv, const float* __restrict__ wdw,
    const float* __restrict__ gg, const float* __restrict__ bb,
    const float* __restrict__ mm, const float* __restrict__ vv,
    float* __restrict__ outq)
{
    int idx = blockIdx.x * blockDim.x + threadIdx.x;
    int l  = idx & (RES - 1);
    int ch = (idx >> 10) & (NHKD - 1);
    int b  = idx >> 18;
    const float* row = qkv + ((size_t)b * HQKV + ch) * RES;
    float x0 = (l > 0)       ? row[l - 1] : 0.0f;
    float x1 = row[l];
    float x2 = (l < RES - 1) ? row[l + 1] : 0.0f;
    float y = x0 * wdw[ch * 3] + x1 * wdw[ch * 3 + 1] + x2 * wdw[ch * 3 + 2];
    float inv = gg[ch] * rsqrtf(vv[ch] + 1e-5f);
    outq[idx] = (y - mm[ch]) * inv + bb[ch];
}

// ---------------- fused attention: broadcast-operand register-tiled version ----
// 512 threads (16 warps); block = (b, h, 32-row n tile).
// smem (floats): q[32d][36] | bias[1024] | dsum[32] | stage[16896] | s[32][1028]
#define NT 32
#define Q_OFF    0
#define BIAS_OFF 1152
#define DSUM_OFF 2176
#define STG_OFF  2208
#define S_OFF    (STG_OFF + 16896)
#define ATTN_SMEM_FLOATS (S_OFF + 32 * 1028)
#define ATTN_SMEM_BYTES  (ATTN_SMEM_FLOATS * 4)

__global__ __launch_bounds__(512, 1) void attn_kernel(
    const float* __restrict__ qbuf, const float* __restrict__ qkv,
    const float* __restrict__ bias, float* __restrict__ outp)
{
    extern __shared__ __align__(16) float sh[];
    float* q_s    = sh + Q_OFF;      // q_s[d*36 + n]
    float* bias_s = sh + BIAS_OFF;
    float* dsum   = sh + DSUM_OFF;
    float* stg    = sh + STG_OFF;    // k: [32][516], v: [128][132]
    float* s_s    = sh + S_OFF;      // [32][1028]

    const int b = blockIdx.z, h = blockIdx.y;
    const int n0 = blockIdx.x * NT;
    const int t = threadIdx.x;
    const int lane = t & 31, wrp = t >> 5;

    const float* qb = qbuf + ((size_t)b * NHKD + h * KD) * RES;
    const float* kb = qkv + ((size_t)b * HQKV + NHKD + h * KD) * RES;
    const float* vb = qkv + ((size_t)b * HQKV + 2 * NHKD + h * DV) * RES;
    const float* ab = bias + h * RES;

    // ---- phase 1: q tile (d-major for broadcast reads) + bias row ----
    for (int i = t; i < 1024; i += 512) {
        int d = i >> 5, nn = i & 31;
        q_s[d * 36 + nn] = qb[d * RES + n0 + nn];
        bias_s[i] = ab[i];
    }
    __syncthreads();

    const int ngrp = wrp & 3;        // 4 groups of 8 n rows
    const int mseg = wrp >> 2;       // 4 m segments
    const int nb = ngrp * 8;

    // ---- phase 2: logits. warp = 8 n x 128 m; q broadcast, k per-lane float4 --
    for (int mt = 0; mt < RES; mt += 512) {
        for (int s = t; s < 4096; s += 512) {
            int d = s >> 7, m4 = (s & 127) << 2;
            *(float4*)&stg[d * 516 + m4] = *(const float4*)&kb[(size_t)d * RES + mt + m4];
        }
        __syncthreads();

        const int ml = mseg * 128 + lane * 4;
        float4 acc[8];
        #pragma unroll
        for (int j = 0; j < 8; j++) acc[j] = make_float4(0.f, 0.f, 0.f, 0.f);

        #pragma unroll 8
        for (int d = 0; d < KD; d++) {
            float4 kv = *(const float4*)&stg[d * 516 + ml];
            float qv[8];
            *(float4*)&qv[0] = *(const float4*)&q_s[d * 36 + nb];
            *(float4*)&qv[4] = *(const float4*)&q_s[d * 36 + nb + 4];
            #pragma unroll
            for (int j = 0; j < 8; j++) {
                acc[j].x = fmaf(qv[j], kv.x, acc[j].x);
                acc[j].y = fmaf(qv[j], kv.y, acc[j].y);
                acc[j].z = fmaf(qv[j], kv.z, acc[j].z);
                acc[j].w = fmaf(qv[j], kv.w, acc[j].w);
            }
        }
        {
            const int mg = mt + ml;
            #pragma unroll
            for (int j = 0; j < 8; j++) {
                int ng = n0 + nb + j;
                float4 r;
                r.x = fmaf(acc[j].x, ATT_SCALE, bias_s[abs(ng - mg)]);
                r.y = fmaf(acc[j].y, ATT_SCALE, bias_s[abs(ng - mg - 1)]);
                r.z = fmaf(acc[j].z, ATT_SCALE, bias_s[abs(ng - mg - 2)]);
                r.w = fmaf(acc[j].w, ATT_SCALE, bias_s[abs(ng - mg - 3)]);
                *(float4*)&s_s[(nb + j) * 1028 + mg] = r;
            }
        }
        __syncthreads();
    }

    // ---- phase 3: softmax per row (16 warps x 2 rows) ----
    #pragma unroll
    for (int rr = 0; rr < 2; rr++) {
        int r = wrp * 2 + rr;
        float* row = s_s + r * 1028;
        float mx = -1e30f;
        for (int i = lane * 4; i < RES; i += 128) {
            float4 x = *(const float4*)&row[i];
            mx = fmaxf(mx, fmaxf(fmaxf(x.x, x.y), fmaxf(x.z, x.w)));
        }
        #pragma unroll
        for (int o = 16; o; o >>= 1) mx = fmaxf(mx, __shfl_xor_sync(0xffffffffu, mx, o));
        float sum = 0.0f;
        for (int i = lane * 4; i < RES; i += 128) {
            float4 x = *(const float4*)&row[i];
            x.x = __expf(x.x - mx); x.y = __expf(x.y - mx);
            x.z = __expf(x.z - mx); x.w = __expf(x.w - mx);
            *(float4*)&row[i] = x;
            sum += (x.x + x.y) + (x.z + x.w);
        }
        #pragma unroll
        for (int o = 16; o; o >>= 1) sum += __shfl_xor_sync(0xffffffffu, sum, o);
        if (lane == 0) dsum[r] = 1.0f / sum;
    }
    __syncthreads();

    // ---- phase 4: out[d][n] = sum_m v[d][m] p[n][m]. lane owns 4 d (strided 32),
    //      warp owns 8 n; p broadcast; 4-way m-split -> smem reduction. ----
    const int msel = mseg;           // m quarter within each staged 128-m tile
    float acc4[4][8];
    #pragma unroll
    for (int i = 0; i < 4; i++)
        #pragma unroll
        for (int j = 0; j < 8; j++) acc4[i][j] = 0.0f;

    for (int mt = 0; mt < RES; mt += 128) {
        for (int s = t; s < 4096; s += 512) {
            int d = s >> 5, m4 = (s & 31) << 2;
            *(float4*)&stg[d * 132 + m4] = *(const float4*)&vb[(size_t)d * RES + mt + m4];
        }
        __syncthreads();

        const float* pb0 = &s_s[nb * 1028 + mt + msel * 32];
        const float* vb0 = &stg[lane * 132 + msel * 32];
        #pragma unroll 2
        for (int mm = 0; mm < 32; mm += 4) {
            float4 v0 = *(const float4*)&vb0[mm];
            float4 v1 = *(const float4*)&vb0[32 * 132 + mm];
            float4 v2 = *(const float4*)&vb0[64 * 132 + mm];
            float4 v3 = *(const float4*)&vb0[96 * 132 + mm];
            #pragma unroll
            for (int j = 0; j < 8; j++) {
                float4 p = *(const float4*)&pb0[j * 1028 + mm];
                acc4[0][j] = fmaf(v0.x, p.x, fmaf(v0.y, p.y, fmaf(v0.z, p.z, fmaf(v0.w, p.w, acc4[0][j]))));
                acc4[1][j] = fmaf(v1.x, p.x, fmaf(v1.y, p.y, fmaf(v1.z, p.z, fmaf(v1.w, p.w, acc4[1][j]))));
                acc4[2][j] = fmaf(v2.x, p.x, fmaf(v2.y, p.y, fmaf(v2.z, p.z, fmaf(v2.w, p.w, acc4[2][j]))));
                acc4[3][j] = fmaf(v3.x, p.x, fmaf(v3.y, p.y, fmaf(v3.z, p.z, fmaf(v3.w, p.w, acc4[3][j]))));
            }
        }
        __syncthreads();
    }

    // partial sums -> smem (reuse s_s): red[msel*4096 + d*32 + n]
    float* red = s_s;
    #pragma unroll
    for (int i = 0; i < 4; i++) {
        int d = lane + 32 * i;
        float4 w0, w1;
        w0.x = acc4[i][0]; w0.y = acc4[i][1]; w0.z = acc4[i][2]; w0.w = acc4[i][3];
        w1.x = acc4[i][4]; w1.y = acc4[i][5]; w1.z = acc4[i][6]; w1.w = acc4[i][7];
        *(float4*)&red[msel * 4096 + d * 32 + nb]     = w0;
        *(float4*)&red[msel * 4096 + d * 32 + nb + 4] = w1;
    }
    __syncthreads();

    // final reduce + relu + scale + store
    {
        const int d  = t >> 2;
        const int nq = (t & 3) * 8;
        float4 s0 = *(const float4*)&red[d * 32 + nq];
        float4 s1 = *(const float4*)&red[d * 32 + nq + 4];
        #pragma unroll
        for (int s = 1; s < 4; s++) {
            float4 a = *(const float4*)&red[s * 4096 + d * 32 + nq];
            float4 c = *(const float4*)&red[s * 4096 + d * 32 + nq + 4];
            s0.x += a.x; s0.y += a.y; s0.z += a.z; s0.w += a.w;
            s1.x += c.x; s1.y += c.y; s1.z += c.z; s1.w += c.w;
        }
        float4 d0 = *(const float4*)&dsum[nq];
        float4 d1 = *(const float4*)&dsum[nq + 4];
        s0.x = fmaxf(s0.x * d0.x, 0.f); s0.y = fmaxf(s0.y * d0.y, 0.f);
        s0.z = fmaxf(s0.z * d0.z, 0.f); s0.w = fmaxf(s0.w * d0.w, 0.f);
        s1.x = fmaxf(s1.x * d1.x, 0.f); s1.y = fmaxf(s1.y * d1.y, 0.f);
        s1.z = fmaxf(s1.z * d1.z, 0.f); s1.w = fmaxf(s1.w * d1.w, 0.f);
        float* ob = outp + ((size_t)b * DHDIM + h * DV) * RES + n0;
        *(float4*)&ob[(size_t)d * RES + nq]     = s0;
        *(float4*)&ob[(size_t)d * RES + nq + 4] = s1;
    }
}

// --------------------------------- launch -------------------------------------
extern "C" void kernel_launch(void* const* d_in, const int* in_sizes, int n_in,
                              void* d_out, int out_size)
{
    const float* x      = (const float*)d_in[0];
    const float* w_qkv  = (const float*)d_in[1];
    const float* qkv_g  = (const float*)d_in[2];
    const float* qkv_b  = (const float*)d_in[3];
    const float* qkv_m  = (const float*)d_in[4];
    const float* qkv_v  = (const float*)d_in[5];
    const float* w_dw   = (const float*)d_in[6];
    const float* dw_g   = (const float*)d_in[7];
    const float* dw_b   = (const float*)d_in[8];
    const float* dw_m   = (const float*)d_in[9];
    const float* dw_v   = (const float*)d_in[10];
    const float* w_proj = (const float*)d_in[11];
    const float* proj_g = (const float*)d_in[12];
    const float* proj_b = (const float*)d_in[13];
    const float* proj_m = (const float*)d_in[14];
    const float* proj_v = (const float*)d_in[15];
    const float* att_bias = (const float*)d_in[16];

    float *p_qkv, *p_q, *p_att;
    cudaGetSymbolAddress((void**)&p_qkv, g_qkv);
    cudaGetSymbolAddress((void**)&p_q,   g_q);
    cudaGetSymbolAddress((void**)&p_att, g_att);

    cudaFuncSetAttribute(attn_kernel, cudaFuncAttributeMaxDynamicSharedMemorySize,
                         ATTN_SMEM_BYTES);

    gemm_bn_kernel<<<dim3(RES / 128, HQKV / 128, BATCH), 128>>>(
        w_qkv, x, qkv_g, qkv_b, qkv_m, qkv_v, p_qkv, HQKV, DIMC, RES);

    dwconv_bn_kernel<<<(BATCH * NHKD * RES) / 256, 256>>>(
        p_qkv, w_dw, dw_g, dw_b, dw_m, dw_v, p_q);

    attn_kernel<<<dim3(RES / NT, NHEAD, BATCH), 512, ATTN_SMEM_BYTES>>>(
        p_q, p_qkv, att_bias, p_att);

    gemm_bn_kernel<<<dim3(RES / 128, DIMC / 128, BATCH), 128>>>(
        w_proj, p_att, proj_g, proj_b, proj_m, proj_v, (float*)d_out,
        DIMC, DHDIM, RES);
}

// round 6
// speedup vs baseline: 1.6252x; 1.6252x over previous
#include <cuda_runtime.h>
#include <math.h>

#define BATCH 16
#define DIMC  512
#define RES   1024
#define NHKD  256
#define HQKV  1536
#define DHDIM 1024
#define NHEAD 8
#define KD    32
#define DV    128
#define ATT_SCALE 0.17677669529663687f

// ---------------- scratch (static device globals; no allocations) -------------
__device__ float g_qkv[BATCH * HQKV * RES];   // 100.7 MB
__device__ float g_q  [BATCH * NHKD * RES];   // 16.8 MB
__device__ float g_att[BATCH * DHDIM * RES];  // 67 MB

// ---------------- tf32 helpers -------------------------------------------------
__device__ __forceinline__ float f2tf(float x) {
    unsigned r;
    asm("cvt.rna.tf32.f32 %0, %1;" : "=r"(r) : "f"(x));
    return __uint_as_float(r);
}
__device__ __forceinline__ void mma_tf32(float c[4], const unsigned a[4],
                                         unsigned b0, unsigned b1) {
    asm volatile(
        "mma.sync.aligned.m16n8k8.row.col.f32.tf32.tf32.f32 "
        "{%0,%1,%2,%3}, {%4,%5,%6,%7}, {%8,%9}, {%0,%1,%2,%3};"
        : "+f"(c[0]), "+f"(c[1]), "+f"(c[2]), "+f"(c[3])
        : "r"(a[0]), "r"(a[1]), "r"(a[2]), "r"(a[3]), "r"(b0), "r"(b1));
}

// ---------------- GEMM (C[b,o,l] = sum_c W[o,c] * X[b,c,l]) + BN, tf32 mma ------
// 128x128 tile, K-chunk 16, 256 threads (8 warps), warp tile 32x64,
// double-buffered smem with conflict-free 136-stride fragment access.
__global__ __launch_bounds__(256) void gemm_tf32_bn(
    const float* __restrict__ W, const float* __restrict__ X,
    const float* __restrict__ gg, const float* __restrict__ bb,
    const float* __restrict__ mm, const float* __restrict__ vv,
    float* __restrict__ out, int O, int C, int L)
{
    __shared__ float As[2][16][136];   // As[k][row]
    __shared__ float Bs[2][16][136];   // Bs[k][col]

    const int b  = blockIdx.z;
    const float* Xb = X + (size_t)b * C * L;
    float* Ob = out + (size_t)b * O * L;
    const int o0 = blockIdx.y * 128;
    const int l0 = blockIdx.x * 128;
    const int t = threadIdx.x, lane = t & 31, wid = t >> 5;
    const int wm = wid & 3, wn = wid >> 2;     // warp tile origin (wm*32, wn*64)
    const int tig = lane & 3, grp = lane >> 2;

    // staging assignments
    const int ar = t & 127, ak = (t >> 7) * 8;  // A: row ar, k ak..ak+7
    const int bk = t >> 5,  blc = (t & 31) * 4; // B: rows bk, bk+8; 4 cols

    float acc[2][8][4];
    #pragma unroll
    for (int m = 0; m < 2; m++)
        #pragma unroll
        for (int j = 0; j < 8; j++)
            #pragma unroll
            for (int r = 0; r < 4; r++) acc[m][j][r] = 0.0f;

    float4 wa0, wa1, xb0, xb1;

    // prefetch chunk 0
    {
        const float* wr = &W[(size_t)(o0 + ar) * C + ak];
        wa0 = *(const float4*)&wr[0];
        wa1 = *(const float4*)&wr[4];
        xb0 = *(const float4*)&Xb[(size_t)bk * L + l0 + blc];
        xb1 = *(const float4*)&Xb[(size_t)(bk + 8) * L + l0 + blc];
    }
    // store chunk 0
    {
        As[0][ak + 0][ar] = f2tf(wa0.x); As[0][ak + 1][ar] = f2tf(wa0.y);
        As[0][ak + 2][ar] = f2tf(wa0.z); As[0][ak + 3][ar] = f2tf(wa0.w);
        As[0][ak + 4][ar] = f2tf(wa1.x); As[0][ak + 5][ar] = f2tf(wa1.y);
        As[0][ak + 6][ar] = f2tf(wa1.z); As[0][ak + 7][ar] = f2tf(wa1.w);
        float4 c0, c1;
        c0.x = f2tf(xb0.x); c0.y = f2tf(xb0.y); c0.z = f2tf(xb0.z); c0.w = f2tf(xb0.w);
        c1.x = f2tf(xb1.x); c1.y = f2tf(xb1.y); c1.z = f2tf(xb1.z); c1.w = f2tf(xb1.w);
        *(float4*)&Bs[0][bk][blc]     = c0;
        *(float4*)&Bs[0][bk + 8][blc] = c1;
    }
    __syncthreads();

    int buf = 0;
    for (int k0 = 16; k0 <= C; k0 += 16) {
        const bool more = (k0 < C);
        if (more) {
            const float* wr = &W[(size_t)(o0 + ar) * C + k0 + ak];
            wa0 = *(const float4*)&wr[0];
            wa1 = *(const float4*)&wr[4];
            xb0 = *(const float4*)&Xb[(size_t)(k0 + bk) * L + l0 + blc];
            xb1 = *(const float4*)&Xb[(size_t)(k0 + bk + 8) * L + l0 + blc];
        }
        // compute on buf
        #pragma unroll
        for (int kk = 0; kk < 2; kk++) {
            unsigned a[2][4];
            #pragma unroll
            for (int m = 0; m < 2; m++) {
                const int row = wm * 32 + m * 16 + grp;
                a[m][0] = __float_as_uint(As[buf][kk * 8 + tig    ][row]);
                a[m][1] = __float_as_uint(As[buf][kk * 8 + tig    ][row + 8]);
                a[m][2] = __float_as_uint(As[buf][kk * 8 + tig + 4][row]);
                a[m][3] = __float_as_uint(As[buf][kk * 8 + tig + 4][row + 8]);
            }
            #pragma unroll
            for (int j = 0; j < 8; j++) {
                const int col = wn * 64 + j * 8 + grp;
                unsigned b0 = __float_as_uint(Bs[buf][kk * 8 + tig    ][col]);
                unsigned b1 = __float_as_uint(Bs[buf][kk * 8 + tig + 4][col]);
                mma_tf32(acc[0][j], a[0], b0, b1);
                mma_tf32(acc[1][j], a[1], b0, b1);
            }
        }
        if (more) {
            const int nb = buf ^ 1;
            As[nb][ak + 0][ar] = f2tf(wa0.x); As[nb][ak + 1][ar] = f2tf(wa0.y);
            As[nb][ak + 2][ar] = f2tf(wa0.z); As[nb][ak + 3][ar] = f2tf(wa0.w);
            As[nb][ak + 4][ar] = f2tf(wa1.x); As[nb][ak + 5][ar] = f2tf(wa1.y);
            As[nb][ak + 6][ar] = f2tf(wa1.z); As[nb][ak + 7][ar] = f2tf(wa1.w);
            float4 c0, c1;
            c0.x = f2tf(xb0.x); c0.y = f2tf(xb0.y); c0.z = f2tf(xb0.z); c0.w = f2tf(xb0.w);
            c1.x = f2tf(xb1.x); c1.y = f2tf(xb1.y); c1.z = f2tf(xb1.z); c1.w = f2tf(xb1.w);
            *(float4*)&Bs[nb][bk][blc]     = c0;
            *(float4*)&Bs[nb][bk + 8][blc] = c1;
            __syncthreads();
        }
        buf ^= 1;
    }

    // epilogue: BN + store (c0,c1 -> row r0 cols l,l+1 ; c2,c3 -> row r0+8)
    #pragma unroll
    for (int m = 0; m < 2; m++) {
        const int r0 = o0 + wm * 32 + m * 16 + grp;
        const int r1 = r0 + 8;
        const float i0 = gg[r0] * rsqrtf(vv[r0] + 1e-5f);
        const float be0 = bb[r0] - mm[r0] * i0;
        const float i1 = gg[r1] * rsqrtf(vv[r1] + 1e-5f);
        const float be1 = bb[r1] - mm[r1] * i1;
        #pragma unroll
        for (int j = 0; j < 8; j++) {
            const int l = l0 + wn * 64 + j * 8 + tig * 2;
            float2 p0, p1;
            p0.x = fmaf(acc[m][j][0], i0, be0);
            p0.y = fmaf(acc[m][j][1], i0, be0);
            p1.x = fmaf(acc[m][j][2], i1, be1);
            p1.y = fmaf(acc[m][j][3], i1, be1);
            *(float2*)&Ob[(size_t)r0 * L + l] = p0;
            *(float2*)&Ob[(size_t)r1 * L + l] = p1;
        }
    }
}

// ---------------- depthwise conv (k=3, pad=1) + BN on q channels ----------------
__global__ __launch_bounds__(256) void dwconv_bn_kernel(
    const float* __restrict__ qkv, const float* __restrict__ wdw,
    const float* __restrict__ gg, const float* __restrict__ bb,
    const float* __restrict__ mm, const float* __restrict__ vv,
    float* __restrict__ outq)
{
    int idx = blockIdx.x * blockDim.x + threadIdx.x;
    int l  = idx & (RES - 1);
    int ch = (idx >> 10) & (NHKD - 1);
    int b  = idx >> 18;
    const float* row = qkv + ((size_t)b * HQKV + ch) * RES;
    float x0 = (l > 0)       ? row[l - 1] : 0.0f;
    float x1 = row[l];
    float x2 = (l < RES - 1) ? row[l + 1] : 0.0f;
    float y = x0 * wdw[ch * 3] + x1 * wdw[ch * 3 + 1] + x2 * wdw[ch * 3 + 2];
    float inv = gg[ch] * rsqrtf(vv[ch] + 1e-5f);
    outq[idx] = (y - mm[ch]) * inv + bb[ch];
}

// ---------------- fused attention (round-3 version: known-good) ----------------
#define NT 32
#define Q_OFF    0                       // [32][33]
#define BIAS_OFF 1056                    // [1024]
#define DSUM_OFF 2080                    // [32]
#define VS_OFF   2112                    // 128*132 = 16896 (also k: 32*260=8320)
#define S_OFF    (VS_OFF + 16896)        // [32][1028]
#define ATTN_SMEM_FLOATS (S_OFF + 32 * 1028)
#define ATTN_SMEM_BYTES  (ATTN_SMEM_FLOATS * 4)

__global__ __launch_bounds__(512) void attn_kernel(
    const float* __restrict__ qbuf, const float* __restrict__ qkv,
    const float* __restrict__ bias, float* __restrict__ outp)
{
    extern __shared__ __align__(16) float sh[];
    float* q_s    = sh + Q_OFF;
    float* bias_s = sh + BIAS_OFF;
    float* dsum   = sh + DSUM_OFF;
    float* vs     = sh + VS_OFF;
    float* s_s    = sh + S_OFF;

    const int b = blockIdx.z, h = blockIdx.y;
    const int n0 = blockIdx.x * NT;
    const int t = threadIdx.x;
    const int lane = t & 31, wrp = t >> 5;

    const float* qb = qbuf + ((size_t)b * NHKD + h * KD) * RES;
    const float* kb = qkv + ((size_t)b * HQKV + NHKD + h * KD) * RES;
    const float* vb = qkv + ((size_t)b * HQKV + 2 * NHKD + h * DV) * RES;
    const float* ab = bias + h * RES;

    for (int i = t; i < KD * NT; i += 512) {
        int d = i >> 5, nn = i & 31;
        q_s[nn * 33 + d] = qb[d * RES + n0 + nn];
    }
    for (int i = t; i < RES; i += 512) bias_s[i] = ab[i];
    __syncthreads();

    const int c0  = lane * 4;
    const int n_a = wrp * 2, n_b = n_a + 1;
    const int ng_a = n0 + n_a, ng_b = n0 + n_b;
    for (int mt = 0; mt < RES; mt += 256) {
        for (int s = t; s < 2048; s += 512) {
            int d = s >> 6, m4 = (s & 63) * 4;
            *(float4*)&vs[d * 260 + m4] = *(const float4*)&kb[d * RES + mt + m4];
        }
        __syncthreads();

        float4 a00 = {0,0,0,0}, a01 = {0,0,0,0}, a10 = {0,0,0,0}, a11 = {0,0,0,0};
        #pragma unroll
        for (int d = 0; d < KD; d++) {
            float qa = q_s[n_a * 33 + d];
            float qbv = q_s[n_b * 33 + d];
            float4 k0 = *(const float4*)&vs[d * 260 + c0];
            float4 k1 = *(const float4*)&vs[d * 260 + 128 + c0];
            a00.x = fmaf(qa, k0.x, a00.x); a00.y = fmaf(qa, k0.y, a00.y);
            a00.z = fmaf(qa, k0.z, a00.z); a00.w = fmaf(qa, k0.w, a00.w);
            a01.x = fmaf(qa, k1.x, a01.x); a01.y = fmaf(qa, k1.y, a01.y);
            a01.z = fmaf(qa, k1.z, a01.z); a01.w = fmaf(qa, k1.w, a01.w);
            a10.x = fmaf(qbv, k0.x, a10.x); a10.y = fmaf(qbv, k0.y, a10.y);
            a10.z = fmaf(qbv, k0.z, a10.z); a10.w = fmaf(qbv, k0.w, a10.w);
            a11.x = fmaf(qbv, k1.x, a11.x); a11.y = fmaf(qbv, k1.y, a11.y);
            a11.z = fmaf(qbv, k1.z, a11.z); a11.w = fmaf(qbv, k1.w, a11.w);
        }
        {
            int m0 = mt + c0, m1 = mt + 128 + c0;
            float4 r;
            r.x = fmaf(a00.x, ATT_SCALE, bias_s[abs(ng_a - (m0 + 0))]);
            r.y = fmaf(a00.y, ATT_SCALE, bias_s[abs(ng_a - (m0 + 1))]);
            r.z = fmaf(a00.z, ATT_SCALE, bias_s[abs(ng_a - (m0 + 2))]);
            r.w = fmaf(a00.w, ATT_SCALE, bias_s[abs(ng_a - (m0 + 3))]);
            *(float4*)&s_s[n_a * 1028 + m0] = r;
            r.x = fmaf(a01.x, ATT_SCALE, bias_s[abs(ng_a - (m1 + 0))]);
            r.y = fmaf(a01.y, ATT_SCALE, bias_s[abs(ng_a - (m1 + 1))]);
            r.z = fmaf(a01.z, ATT_SCALE, bias_s[abs(ng_a - (m1 + 2))]);
            r.w = fmaf(a01.w, ATT_SCALE, bias_s[abs(ng_a - (m1 + 3))]);
            *(float4*)&s_s[n_a * 1028 + m1] = r;
            r.x = fmaf(a10.x, ATT_SCALE, bias_s[abs(ng_b - (m0 + 0))]);
            r.y = fmaf(a10.y, ATT_SCALE, bias_s[abs(ng_b - (m0 + 1))]);
            r.z = fmaf(a10.z, ATT_SCALE, bias_s[abs(ng_b - (m0 + 2))]);
            r.w = fmaf(a10.w, ATT_SCALE, bias_s[abs(ng_b - (m0 + 3))]);
            *(float4*)&s_s[n_b * 1028 + m0] = r;
            r.x = fmaf(a11.x, ATT_SCALE, bias_s[abs(ng_b - (m1 + 0))]);
            r.y = fmaf(a11.y, ATT_SCALE, bias_s[abs(ng_b - (m1 + 1))]);
            r.z = fmaf(a11.z, ATT_SCALE, bias_s[abs(ng_b - (m1 + 2))]);
            r.w = fmaf(a11.w, ATT_SCALE, bias_s[abs(ng_b - (m1 + 3))]);
            *(float4*)&s_s[n_b * 1028 + m1] = r;
        }
        __syncthreads();
    }

    #pragma unroll
    for (int rr = 0; rr < 2; rr++) {
        int r = wrp * 2 + rr;
        float* row = s_s + r * 1028;
        float mx = -1e30f;
        for (int i = lane * 4; i < RES; i += 128) {
            float4 x = *(const float4*)&row[i];
            mx = fmaxf(mx, fmaxf(fmaxf(x.x, x.y), fmaxf(x.z, x.w)));
        }
        #pragma unroll
        for (int o = 16; o; o >>= 1) mx = fmaxf(mx, __shfl_xor_sync(0xffffffffu, mx, o));
        float sum = 0.0f;
        for (int i = lane * 4; i < RES; i += 128) {
            float4 x = *(const float4*)&row[i];
            x.x = __expf(x.x - mx); x.y = __expf(x.y - mx);
            x.z = __expf(x.z - mx); x.w = __expf(x.w - mx);
            *(float4*)&row[i] = x;
            sum += (x.x + x.y) + (x.z + x.w);
        }
        #pragma unroll
        for (int o = 16; o; o >>= 1) sum += __shfl_xor_sync(0xffffffffu, sum, o);
        if (lane == 0) dsum[r] = 1.0f / sum;
    }
    __syncthreads();

    const int dg = t & 63;
    const int nq = (t >> 6) * 4;
    float4 oa0 = {0,0,0,0}, oa1 = {0,0,0,0};
    for (int mt = 0; mt < RES; mt += 128) {
        for (int s = t; s < 4096; s += 512) {
            int d = s >> 5, m4 = (s & 31) * 4;
            *(float4*)&vs[d * 132 + m4] = *(const float4*)&vb[d * RES + mt + m4];
        }
        __syncthreads();
        #pragma unroll 4
        for (int m4 = 0; m4 < 128; m4 += 4) {
            float4 v0 = *(const float4*)&vs[dg * 132 + m4];
            float4 v1 = *(const float4*)&vs[(dg + 64) * 132 + m4];
            float4 p0 = *(const float4*)&s_s[(nq + 0) * 1028 + mt + m4];
            float4 p1 = *(const float4*)&s_s[(nq + 1) * 1028 + mt + m4];
            float4 p2 = *(const float4*)&s_s[(nq + 2) * 1028 + mt + m4];
            float4 p3 = *(const float4*)&s_s[(nq + 3) * 1028 + mt + m4];
            oa0.x = fmaf(v0.x, p0.x, fmaf(v0.y, p0.y, fmaf(v0.z, p0.z, fmaf(v0.w, p0.w, oa0.x))));
            oa0.y = fmaf(v0.x, p1.x, fmaf(v0.y, p1.y, fmaf(v0.z, p1.z, fmaf(v0.w, p1.w, oa0.y))));
            oa0.z = fmaf(v0.x, p2.x, fmaf(v0.y, p2.y, fmaf(v0.z, p2.z, fmaf(v0.w, p2.w, oa0.z))));
            oa0.w = fmaf(v0.x, p3.x, fmaf(v0.y, p3.y, fmaf(v0.z, p3.z, fmaf(v0.w, p3.w, oa0.w))));
            oa1.x = fmaf(v1.x, p0.x, fmaf(v1.y, p0.y, fmaf(v1.z, p0.z, fmaf(v1.w, p0.w, oa1.x))));
            oa1.y = fmaf(v1.x, p1.x, fmaf(v1.y, p1.y, fmaf(v1.z, p1.z, fmaf(v1.w, p1.w, oa1.y))));
            oa1.z = fmaf(v1.x, p2.x, fmaf(v1.y, p2.y, fmaf(v1.z, p2.z, fmaf(v1.w, p2.w, oa1.z))));
            oa1.w = fmaf(v1.x, p3.x, fmaf(v1.y, p3.y, fmaf(v1.z, p3.z, fmaf(v1.w, p3.w, oa1.w))));
        }
        __syncthreads();
    }

    {
        float d0 = dsum[nq + 0], d1 = dsum[nq + 1], d2 = dsum[nq + 2], d3 = dsum[nq + 3];
        float* ob = outp + ((size_t)b * DHDIM + h * DV) * RES + n0;
        float4 w0, w1;
        w0.x = fmaxf(oa0.x * d0, 0.0f); w0.y = fmaxf(oa0.y * d1, 0.0f);
        w0.z = fmaxf(oa0.z * d2, 0.0f); w0.w = fmaxf(oa0.w * d3, 0.0f);
        w1.x = fmaxf(oa1.x * d0, 0.0f); w1.y = fmaxf(oa1.y * d1, 0.0f);
        w1.z = fmaxf(oa1.z * d2, 0.0f); w1.w = fmaxf(oa1.w * d3, 0.0f);
        *(float4*)&ob[(size_t)dg * RES + nq]        = w0;
        *(float4*)&ob[(size_t)(dg + 64) * RES + nq] = w1;
    }
}

// --------------------------------- launch -------------------------------------
extern "C" void kernel_launch(void* const* d_in, const int* in_sizes, int n_in,
                              void* d_out, int out_size)
{
    const float* x      = (const float*)d_in[0];
    const float* w_qkv  = (const float*)d_in[1];
    const float* qkv_g  = (const float*)d_in[2];
    const float* qkv_b  = (const float*)d_in[3];
    const float* qkv_m  = (const float*)d_in[4];
    const float* qkv_v  = (const float*)d_in[5];
    const float* w_dw   = (const float*)d_in[6];
    const float* dw_g   = (const float*)d_in[7];
    const float* dw_b   = (const float*)d_in[8];
    const float* dw_m   = (const float*)d_in[9];
    const float* dw_v   = (const float*)d_in[10];
    const float* w_proj = (const float*)d_in[11];
    const float* proj_g = (const float*)d_in[12];
    const float* proj_b = (const float*)d_in[13];
    const float* proj_m = (const float*)d_in[14];
    const float* proj_v = (const float*)d_in[15];
    const float* att_bias = (const float*)d_in[16];

    float *p_qkv, *p_q, *p_att;
    cudaGetSymbolAddress((void**)&p_qkv, g_qkv);
    cudaGetSymbolAddress((void**)&p_q,   g_q);
    cudaGetSymbolAddress((void**)&p_att, g_att);

    cudaFuncSetAttribute(attn_kernel, cudaFuncAttributeMaxDynamicSharedMemorySize,
                         ATTN_SMEM_BYTES);

    // 1) QKV GEMM + BN : (1536 x 512) x (512 x 1024) per batch, tf32 mma
    gemm_tf32_bn<<<dim3(RES / 128, HQKV / 128, BATCH), 256>>>(
        w_qkv, x, qkv_g, qkv_b, qkv_m, qkv_v, p_qkv, HQKV, DIMC, RES);

    // 2) depthwise conv + BN on q
    dwconv_bn_kernel<<<(BATCH * NHKD * RES) / 256, 256>>>(
        p_qkv, w_dw, dw_g, dw_b, dw_m, dw_v, p_q);

    // 3) fused attention (round-3 version)
    attn_kernel<<<dim3(RES / NT, NHEAD, BATCH), 512, ATTN_SMEM_BYTES>>>(
        p_q, p_qkv, att_bias, p_att);

    // 4) projection GEMM + BN : (512 x 1024) x (1024 x 1024) per batch, tf32 mma
    gemm_tf32_bn<<<dim3(RES / 128, DIMC / 128, BATCH), 256>>>(
        w_proj, p_att, proj_g, proj_b, proj_m, proj_v, (float*)d_out,
        DIMC, DHDIM, RES);
}

// round 7
// speedup vs baseline: 2.5373x; 1.5612x over previous
#include <cuda_runtime.h>
#include <math.h>

#define BATCH 16
#define DIMC  512
#define RES   1024
#define NHKD  256
#define HQKV  1536
#define DHDIM 1024
#define NHEAD 8
#define KD    32
#define DV    128
#define ATT_SCALE 0.17677669529663687f

// ---------------- scratch (static device globals; no allocations) -------------
__device__ float g_qkv[BATCH * HQKV * RES];   // 100.7 MB
__device__ float g_q  [BATCH * NHKD * RES];   // 16.8 MB
__device__ float g_att[BATCH * DHDIM * RES];  // 67 MB

// ---------------- tf32 helpers -------------------------------------------------
__device__ __forceinline__ float f2tf(float x) {
    unsigned r;
    asm("cvt.rna.tf32.f32 %0, %1;" : "=r"(r) : "f"(x));
    return __uint_as_float(r);
}
__device__ __forceinline__ void mma_tf32(float c[4], const float a[4],
                                         float b0, float b1) {
    asm volatile(
        "mma.sync.aligned.m16n8k8.row.col.f32.tf32.tf32.f32 "
        "{%0,%1,%2,%3}, {%4,%5,%6,%7}, {%8,%9}, {%0,%1,%2,%3};"
        : "+f"(c[0]), "+f"(c[1]), "+f"(c[2]), "+f"(c[3])
        : "r"(__float_as_uint(a[0])), "r"(__float_as_uint(a[1])),
          "r"(__float_as_uint(a[2])), "r"(__float_as_uint(a[3])),
          "r"(__float_as_uint(b0)), "r"(__float_as_uint(b1)));
}

// ---------------- GEMM (C[b,o,l] = sum_c W[o,c] * X[b,c,l]) + BN, tf32 mma ------
__global__ __launch_bounds__(256) void gemm_tf32_bn(
    const float* __restrict__ W, const float* __restrict__ X,
    const float* __restrict__ gg, const float* __restrict__ bb,
    const float* __restrict__ mm, const float* __restrict__ vv,
    float* __restrict__ out, int O, int C, int L)
{
    __shared__ float As[2][16][136];
    __shared__ float Bs[2][16][136];

    const int b  = blockIdx.z;
    const float* Xb = X + (size_t)b * C * L;
    float* Ob = out + (size_t)b * O * L;
    const int o0 = blockIdx.y * 128;
    const int l0 = blockIdx.x * 128;
    const int t = threadIdx.x, lane = t & 31, wid = t >> 5;
    const int wm = wid & 3, wn = wid >> 2;
    const int tig = lane & 3, grp = lane >> 2;

    const int ar = t & 127, ak = (t >> 7) * 8;
    const int bk = t >> 5,  blc = (t & 31) * 4;

    float acc[2][8][4];
    #pragma unroll
    for (int m = 0; m < 2; m++)
        #pragma unroll
        for (int j = 0; j < 8; j++)
            #pragma unroll
            for (int r = 0; r < 4; r++) acc[m][j][r] = 0.0f;

    float4 wa0, wa1, xb0, xb1;
    {
        const float* wr = &W[(size_t)(o0 + ar) * C + ak];
        wa0 = *(const float4*)&wr[0];
        wa1 = *(const float4*)&wr[4];
        xb0 = *(const float4*)&Xb[(size_t)bk * L + l0 + blc];
        xb1 = *(const float4*)&Xb[(size_t)(bk + 8) * L + l0 + blc];
    }
    {
        As[0][ak + 0][ar] = f2tf(wa0.x); As[0][ak + 1][ar] = f2tf(wa0.y);
        As[0][ak + 2][ar] = f2tf(wa0.z); As[0][ak + 3][ar] = f2tf(wa0.w);
        As[0][ak + 4][ar] = f2tf(wa1.x); As[0][ak + 5][ar] = f2tf(wa1.y);
        As[0][ak + 6][ar] = f2tf(wa1.z); As[0][ak + 7][ar] = f2tf(wa1.w);
        float4 c0, c1;
        c0.x = f2tf(xb0.x); c0.y = f2tf(xb0.y); c0.z = f2tf(xb0.z); c0.w = f2tf(xb0.w);
        c1.x = f2tf(xb1.x); c1.y = f2tf(xb1.y); c1.z = f2tf(xb1.z); c1.w = f2tf(xb1.w);
        *(float4*)&Bs[0][bk][blc]     = c0;
        *(float4*)&Bs[0][bk + 8][blc] = c1;
    }
    __syncthreads();

    int buf = 0;
    for (int k0 = 16; k0 <= C; k0 += 16) {
        const bool more = (k0 < C);
        if (more) {
            const float* wr = &W[(size_t)(o0 + ar) * C + k0 + ak];
            wa0 = *(const float4*)&wr[0];
            wa1 = *(const float4*)&wr[4];
            xb0 = *(const float4*)&Xb[(size_t)(k0 + bk) * L + l0 + blc];
            xb1 = *(const float4*)&Xb[(size_t)(k0 + bk + 8) * L + l0 + blc];
        }
        #pragma unroll
        for (int kk = 0; kk < 2; kk++) {
            float a[2][4];
            #pragma unroll
            for (int m = 0; m < 2; m++) {
                const int row = wm * 32 + m * 16 + grp;
                a[m][0] = As[buf][kk * 8 + tig    ][row];
                a[m][1] = As[buf][kk * 8 + tig    ][row + 8];
                a[m][2] = As[buf][kk * 8 + tig + 4][row];
                a[m][3] = As[buf][kk * 8 + tig + 4][row + 8];
            }
            #pragma unroll
            for (int j = 0; j < 8; j++) {
                const int col = wn * 64 + j * 8 + grp;
                float b0 = Bs[buf][kk * 8 + tig    ][col];
                float b1 = Bs[buf][kk * 8 + tig + 4][col];
                mma_tf32(acc[0][j], a[0], b0, b1);
                mma_tf32(acc[1][j], a[1], b0, b1);
            }
        }
        if (more) {
            const int nb = buf ^ 1;
            As[nb][ak + 0][ar] = f2tf(wa0.x); As[nb][ak + 1][ar] = f2tf(wa0.y);
            As[nb][ak + 2][ar] = f2tf(wa0.z); As[nb][ak + 3][ar] = f2tf(wa0.w);
            As[nb][ak + 4][ar] = f2tf(wa1.x); As[nb][ak + 5][ar] = f2tf(wa1.y);
            As[nb][ak + 6][ar] = f2tf(wa1.z); As[nb][ak + 7][ar] = f2tf(wa1.w);
            float4 c0, c1;
            c0.x = f2tf(xb0.x); c0.y = f2tf(xb0.y); c0.z = f2tf(xb0.z); c0.w = f2tf(xb0.w);
            c1.x = f2tf(xb1.x); c1.y = f2tf(xb1.y); c1.z = f2tf(xb1.z); c1.w = f2tf(xb1.w);
            *(float4*)&Bs[nb][bk][blc]     = c0;
            *(float4*)&Bs[nb][bk + 8][blc] = c1;
            __syncthreads();
        }
        buf ^= 1;
    }

    #pragma unroll
    for (int m = 0; m < 2; m++) {
        const int r0 = o0 + wm * 32 + m * 16 + grp;
        const int r1 = r0 + 8;
        const float i0 = gg[r0] * rsqrtf(vv[r0] + 1e-5f);
        const float be0 = bb[r0] - mm[r0] * i0;
        const float i1 = gg[r1] * rsqrtf(vv[r1] + 1e-5f);
        const float be1 = bb[r1] - mm[r1] * i1;
        #pragma unroll
        for (int j = 0; j < 8; j++) {
            const int l = l0 + wn * 64 + j * 8 + tig * 2;
            float2 p0, p1;
            p0.x = fmaf(acc[m][j][0], i0, be0);
            p0.y = fmaf(acc[m][j][1], i0, be0);
            p1.x = fmaf(acc[m][j][2], i1, be1);
            p1.y = fmaf(acc[m][j][3], i1, be1);
            *(float2*)&Ob[(size_t)r0 * L + l] = p0;
            *(float2*)&Ob[(size_t)r1 * L + l] = p1;
        }
    }
}

// ---------------- depthwise conv (k=3, pad=1) + BN on q channels ----------------
__global__ __launch_bounds__(256) void dwconv_bn_kernel(
    const float* __restrict__ qkv, const float* __restrict__ wdw,
    const float* __restrict__ gg, const float* __restrict__ bb,
    const float* __restrict__ mm, const float* __restrict__ vv,
    float* __restrict__ outq)
{
    int idx = blockIdx.x * blockDim.x + threadIdx.x;
    int l  = idx & (RES - 1);
    int ch = (idx >> 10) & (NHKD - 1);
    int b  = idx >> 18;
    const float* row = qkv + ((size_t)b * HQKV + ch) * RES;
    float x0 = (l > 0)       ? row[l - 1] : 0.0f;
    float x1 = row[l];
    float x2 = (l < RES - 1) ? row[l + 1] : 0.0f;
    float y = x0 * wdw[ch * 3] + x1 * wdw[ch * 3 + 1] + x2 * wdw[ch * 3 + 2];
    float inv = gg[ch] * rsqrtf(vv[ch] + 1e-5f);
    outq[idx] = (y - mm[ch]) * inv + bb[ch];
}

// ---------------- fused attention, tf32 mma for q.k and p.v --------------------
// 512 threads (16 warps); block = (b, h, 32-row n tile).
#define NT 32
#define Q_OFF    0                       // q_s[n][36] (tf32)
#define BIAS_OFF 1152                    // [1024]
#define DSUM_OFF 2176                    // [32]
#define STG_OFF  2208                    // k: [32][260]=8320 ; v: [128][132]=16896
#define S_OFF    (STG_OFF + 16896)       // s_s[32][1028]
#define ATTN_SMEM_FLOATS (S_OFF + 32 * 1028)
#define ATTN_SMEM_BYTES  (ATTN_SMEM_FLOATS * 4)

__global__ __launch_bounds__(512, 1) void attn_kernel(
    const float* __restrict__ qbuf, const float* __restrict__ qkv,
    const float* __restrict__ bias, float* __restrict__ outp)
{
    extern __shared__ __align__(16) float sh[];
    float* q_s    = sh + Q_OFF;
    float* bias_s = sh + BIAS_OFF;
    float* dsum   = sh + DSUM_OFF;
    float* stg    = sh + STG_OFF;
    float* s_s    = sh + S_OFF;

    const int b = blockIdx.z, h = blockIdx.y;
    const int n0 = blockIdx.x * NT;
    const int t = threadIdx.x;
    const int lane = t & 31, wrp = t >> 5;
    const int grp = lane >> 2, tig = lane & 3;

    const float* qb = qbuf + ((size_t)b * NHKD + h * KD) * RES;
    const float* kb = qkv + ((size_t)b * HQKV + NHKD + h * KD) * RES;
    const float* vb = qkv + ((size_t)b * HQKV + 2 * NHKD + h * DV) * RES;
    const float* ab = bias + h * RES;

    // ---- phase 1: q tile (n-major, tf32) + bias row ----
    for (int i = t; i < 1024; i += 512) {
        int d = i >> 5, nn = i & 31;
        q_s[nn * 36 + d] = f2tf(qb[d * RES + n0 + nn]);
        bias_s[i] = ab[i];
    }
    __syncthreads();

    // ---- phase 2: S = scale*(q k) + bias via mma ----
    // warp: nhalf (16 rows) x 32 m-cols inside each 256-m chunk.
    {
        const int nhalf = wrp & 1;
        const int msub  = wrp >> 1;          // 0..7 -> 32-m slice
        const int nrow0 = nhalf * 16 + grp;

        float aq[4][4];
        #pragma unroll
        for (int kk = 0; kk < 4; kk++) {
            aq[kk][0] = q_s[nrow0 * 36 + kk * 8 + tig];
            aq[kk][1] = q_s[(nrow0 + 8) * 36 + kk * 8 + tig];
            aq[kk][2] = q_s[nrow0 * 36 + kk * 8 + tig + 4];
            aq[kk][3] = q_s[(nrow0 + 8) * 36 + kk * 8 + tig + 4];
        }

        for (int mt = 0; mt < RES; mt += 256) {
            for (int s = t; s < 2048; s += 512) {
                int d = s >> 6, m4 = (s & 63) * 4;
                float4 kv = *(const float4*)&kb[(size_t)d * RES + mt + m4];
                float4 c;
                c.x = f2tf(kv.x); c.y = f2tf(kv.y); c.z = f2tf(kv.z); c.w = f2tf(kv.w);
                *(float4*)&stg[d * 260 + m4] = c;
            }
            __syncthreads();

            float acc[4][4];
            #pragma unroll
            for (int j = 0; j < 4; j++)
                #pragma unroll
                for (int r = 0; r < 4; r++) acc[j][r] = 0.0f;

            #pragma unroll
            for (int kk = 0; kk < 4; kk++) {
                #pragma unroll
                for (int j = 0; j < 4; j++) {
                    const int mc = msub * 32 + j * 8 + grp;
                    float b0 = stg[(kk * 8 + tig) * 260 + mc];
                    float b1 = stg[(kk * 8 + tig + 4) * 260 + mc];
                    mma_tf32(acc[j], aq[kk], b0, b1);
                }
            }
            // epilogue: scale + bias -> s_s (fp32)
            #pragma unroll
            for (int j = 0; j < 4; j++) {
                const int mg = mt + msub * 32 + j * 8 + tig * 2;
                const int ngA = n0 + nrow0, ngB = ngA + 8;
                float2 p0, p1;
                p0.x = fmaf(acc[j][0], ATT_SCALE, bias_s[abs(ngA - mg)]);
                p0.y = fmaf(acc[j][1], ATT_SCALE, bias_s[abs(ngA - mg - 1)]);
                p1.x = fmaf(acc[j][2], ATT_SCALE, bias_s[abs(ngB - mg)]);
                p1.y = fmaf(acc[j][3], ATT_SCALE, bias_s[abs(ngB - mg - 1)]);
                *(float2*)&s_s[nrow0 * 1028 + mg]       = p0;
                *(float2*)&s_s[(nrow0 + 8) * 1028 + mg] = p1;
            }
            __syncthreads();
        }
    }

    // ---- phase 3: softmax per row; store exp as tf32 ----
    #pragma unroll
    for (int rr = 0; rr < 2; rr++) {
        int r = wrp * 2 + rr;
        float* row = s_s + r * 1028;
        float mx = -1e30f;
        for (int i = lane * 4; i < RES; i += 128) {
            float4 x = *(const float4*)&row[i];
            mx = fmaxf(mx, fmaxf(fmaxf(x.x, x.y), fmaxf(x.z, x.w)));
        }
        #pragma unroll
        for (int o = 16; o; o >>= 1) mx = fmaxf(mx, __shfl_xor_sync(0xffffffffu, mx, o));
        float sum = 0.0f;
        for (int i = lane * 4; i < RES; i += 128) {
            float4 x = *(const float4*)&row[i];
            x.x = __expf(x.x - mx); x.y = __expf(x.y - mx);
            x.z = __expf(x.z - mx); x.w = __expf(x.w - mx);
            sum += (x.x + x.y) + (x.z + x.w);
            x.x = f2tf(x.x); x.y = f2tf(x.y); x.z = f2tf(x.z); x.w = f2tf(x.w);
            *(float4*)&row[i] = x;
        }
        #pragma unroll
        for (int o = 16; o; o >>= 1) sum += __shfl_xor_sync(0xffffffffu, sum, o);
        if (lane == 0) dsum[r] = 1.0f / sum;
    }
    __syncthreads();

    // ---- phase 4: out[d][n] = sum_m v[d][m] p[n][m] via mma ----
    // warp: d16 tile (wrp>>1) x two n8 tiles ((wrp&1)*16 .. +15), K = 1024.
    {
        const int d0 = (wrp >> 1) * 16;
        const int nb = (wrp & 1) * 16;
        float c[2][4];
        #pragma unroll
        for (int tn = 0; tn < 2; tn++)
            #pragma unroll
            for (int r = 0; r < 4; r++) c[tn][r] = 0.0f;

        for (int mt = 0; mt < RES; mt += 128) {
            for (int s = t; s < 4096; s += 512) {
                int d = s >> 5, m4 = (s & 31) * 4;
                float4 vv4 = *(const float4*)&vb[(size_t)d * RES + mt + m4];
                float4 cc;
                cc.x = f2tf(vv4.x); cc.y = f2tf(vv4.y); cc.z = f2tf(vv4.z); cc.w = f2tf(vv4.w);
                *(float4*)&stg[d * 132 + m4] = cc;
            }
            __syncthreads();

            #pragma unroll 4
            for (int kk = 0; kk < 16; kk++) {
                float av[4];
                av[0] = stg[(d0 + grp) * 132 + kk * 8 + tig];
                av[1] = stg[(d0 + grp + 8) * 132 + kk * 8 + tig];
                av[2] = stg[(d0 + grp) * 132 + kk * 8 + tig + 4];
                av[3] = stg[(d0 + grp + 8) * 132 + kk * 8 + tig + 4];
                #pragma unroll
                for (int tn = 0; tn < 2; tn++) {
                    const int nrow = nb + tn * 8 + grp;
                    float b0 = s_s[nrow * 1028 + mt + kk * 8 + tig];
                    float b1 = s_s[nrow * 1028 + mt + kk * 8 + tig + 4];
                    mma_tf32(c[tn], av, b0, b1);
                }
            }
            __syncthreads();
        }

        // epilogue: /sum, relu, store
        float* ob = outp + ((size_t)b * DHDIM + h * DV) * RES + n0;
        #pragma unroll
        for (int tn = 0; tn < 2; tn++) {
            const int ncol = nb + tn * 8 + tig * 2;
            const float s0 = dsum[ncol], s1 = dsum[ncol + 1];
            float2 p0, p1;
            p0.x = fmaxf(c[tn][0] * s0, 0.0f);
            p0.y = fmaxf(c[tn][1] * s1, 0.0f);
            p1.x = fmaxf(c[tn][2] * s0, 0.0f);
            p1.y = fmaxf(c[tn][3] * s1, 0.0f);
            *(float2*)&ob[(size_t)(d0 + grp) * RES + ncol]     = p0;
            *(float2*)&ob[(size_t)(d0 + grp + 8) * RES + ncol] = p1;
        }
    }
}

// --------------------------------- launch -------------------------------------
extern "C" void kernel_launch(void* const* d_in, const int* in_sizes, int n_in,
                              void* d_out, int out_size)
{
    const float* x      = (const float*)d_in[0];
    const float* w_qkv  = (const float*)d_in[1];
    const float* qkv_g  = (const float*)d_in[2];
    const float* qkv_b  = (const float*)d_in[3];
    const float* qkv_m  = (const float*)d_in[4];
    const float* qkv_v  = (const float*)d_in[5];
    const float* w_dw   = (const float*)d_in[6];
    const float* dw_g   = (const float*)d_in[7];
    const float* dw_b   = (const float*)d_in[8];
    const float* dw_m   = (const float*)d_in[9];
    const float* dw_v   = (const float*)d_in[10];
    const float* w_proj = (const float*)d_in[11];
    const float* proj_g = (const float*)d_in[12];
    const float* proj_b = (const float*)d_in[13];
    const float* proj_m = (const float*)d_in[14];
    const float* proj_v = (const float*)d_in[15];
    const float* att_bias = (const float*)d_in[16];

    float *p_qkv, *p_q, *p_att;
    cudaGetSymbolAddress((void**)&p_qkv, g_qkv);
    cudaGetSymbolAddress((void**)&p_q,   g_q);
    cudaGetSymbolAddress((void**)&p_att, g_att);

    cudaFuncSetAttribute(attn_kernel, cudaFuncAttributeMaxDynamicSharedMemorySize,
                         ATTN_SMEM_BYTES);

    gemm_tf32_bn<<<dim3(RES / 128, HQKV / 128, BATCH), 256>>>(
        w_qkv, x, qkv_g, qkv_b, qkv_m, qkv_v, p_qkv, HQKV, DIMC, RES);

    dwconv_bn_kernel<<<(BATCH * NHKD * RES) / 256, 256>>>(
        p_qkv, w_dw, dw_g, dw_b, dw_m, dw_v, p_q);

    attn_kernel<<<dim3(RES / NT, NHEAD, BATCH), 512, ATTN_SMEM_BYTES>>>(
        p_q, p_qkv, att_bias, p_att);

    gemm_tf32_bn<<<dim3(RES / 128, DIMC / 128, BATCH), 256>>>(
        w_proj, p_att, proj_g, proj_b, proj_m, proj_v, (float*)d_out,
        DIMC, DHDIM, RES);
}

// round 8
// speedup vs baseline: 3.3643x; 1.3259x over previous
#include <cuda_runtime.h>
#include <math.h>

#define BATCH 16
#define DIMC  512
#define RES   1024
#define NHKD  256
#define HQKV  1536
#define DHDIM 1024
#define NHEAD 8
#define KD    32
#define DV    128
#define ATT_SCALE 0.17677669529663687f

// ---------------- scratch (static device globals; no allocations) -------------
__device__ float g_qkv[BATCH * HQKV * RES];
__device__ float g_q  [BATCH * NHKD * RES];
__device__ float g_att[BATCH * DHDIM * RES];

// ---------------- tf32 / cp.async helpers --------------------------------------
__device__ __forceinline__ float f2tf(float x) {
    unsigned r;
    asm("cvt.rna.tf32.f32 %0, %1;" : "=r"(r) : "f"(x));
    return __uint_as_float(r);
}
__device__ __forceinline__ void mma_tf32(float c[4], const float a[4],
                                         float b0, float b1) {
    asm volatile(
        "mma.sync.aligned.m16n8k8.row.col.f32.tf32.tf32.f32 "
        "{%0,%1,%2,%3}, {%4,%5,%6,%7}, {%8,%9}, {%0,%1,%2,%3};"
        : "+f"(c[0]), "+f"(c[1]), "+f"(c[2]), "+f"(c[3])
        : "r"(__float_as_uint(a[0])), "r"(__float_as_uint(a[1])),
          "r"(__float_as_uint(a[2])), "r"(__float_as_uint(a[3])),
          "r"(__float_as_uint(b0)), "r"(__float_as_uint(b1)));
}
#define CP16(dst, src) \
    asm volatile("cp.async.cg.shared.global [%0], [%1], 16;" :: "r"(dst), "l"(src))
#define CP_COMMIT() asm volatile("cp.async.commit_group;")
#define CP_WAIT0()  asm volatile("cp.async.wait_group 0;")
#define CP_WAIT1()  asm volatile("cp.async.wait_group 1;")

// ---------------- GEMM (C[b,o,l] = sum_c W[o,c] * X[b,c,l]) + BN, tf32 mma ------
__global__ __launch_bounds__(256) void gemm_tf32_bn(
    const float* __restrict__ W, const float* __restrict__ X,
    const float* __restrict__ gg, const float* __restrict__ bb,
    const float* __restrict__ mm, const float* __restrict__ vv,
    float* __restrict__ out, int O, int C, int L)
{
    __shared__ float As[2][16][136];
    __shared__ float Bs[2][16][136];

    const int b  = blockIdx.z;
    const float* Xb = X + (size_t)b * C * L;
    float* Ob = out + (size_t)b * O * L;
    const int o0 = blockIdx.y * 128;
    const int l0 = blockIdx.x * 128;
    const int t = threadIdx.x, lane = t & 31, wid = t >> 5;
    const int wm = wid & 3, wn = wid >> 2;
    const int tig = lane & 3, grp = lane >> 2;

    const int ar = t & 127, ak = (t >> 7) * 8;
    const int bk = t >> 5,  blc = (t & 31) * 4;

    float acc[2][8][4];
    #pragma unroll
    for (int m = 0; m < 2; m++)
        #pragma unroll
        for (int j = 0; j < 8; j++)
            #pragma unroll
            for (int r = 0; r < 4; r++) acc[m][j][r] = 0.0f;

    float4 wa0, wa1, xb0, xb1;
    {
        const float* wr = &W[(size_t)(o0 + ar) * C + ak];
        wa0 = *(const float4*)&wr[0];
        wa1 = *(const float4*)&wr[4];
        xb0 = *(const float4*)&Xb[(size_t)bk * L + l0 + blc];
        xb1 = *(const float4*)&Xb[(size_t)(bk + 8) * L + l0 + blc];
    }
    {
        As[0][ak + 0][ar] = f2tf(wa0.x); As[0][ak + 1][ar] = f2tf(wa0.y);
        As[0][ak + 2][ar] = f2tf(wa0.z); As[0][ak + 3][ar] = f2tf(wa0.w);
        As[0][ak + 4][ar] = f2tf(wa1.x); As[0][ak + 5][ar] = f2tf(wa1.y);
        As[0][ak + 6][ar] = f2tf(wa1.z); As[0][ak + 7][ar] = f2tf(wa1.w);
        float4 c0, c1;
        c0.x = f2tf(xb0.x); c0.y = f2tf(xb0.y); c0.z = f2tf(xb0.z); c0.w = f2tf(xb0.w);
        c1.x = f2tf(xb1.x); c1.y = f2tf(xb1.y); c1.z = f2tf(xb1.z); c1.w = f2tf(xb1.w);
        *(float4*)&Bs[0][bk][blc]     = c0;
        *(float4*)&Bs[0][bk + 8][blc] = c1;
    }
    __syncthreads();

    int buf = 0;
    for (int k0 = 16; k0 <= C; k0 += 16) {
        const bool more = (k0 < C);
        if (more) {
            const float* wr = &W[(size_t)(o0 + ar) * C + k0 + ak];
            wa0 = *(const float4*)&wr[0];
            wa1 = *(const float4*)&wr[4];
            xb0 = *(const float4*)&Xb[(size_t)(k0 + bk) * L + l0 + blc];
            xb1 = *(const float4*)&Xb[(size_t)(k0 + bk + 8) * L + l0 + blc];
        }
        #pragma unroll
        for (int kk = 0; kk < 2; kk++) {
            float a[2][4];
            #pragma unroll
            for (int m = 0; m < 2; m++) {
                const int row = wm * 32 + m * 16 + grp;
                a[m][0] = As[buf][kk * 8 + tig    ][row];
                a[m][1] = As[buf][kk * 8 + tig    ][row + 8];
                a[m][2] = As[buf][kk * 8 + tig + 4][row];
                a[m][3] = As[buf][kk * 8 + tig + 4][row + 8];
            }
            #pragma unroll
            for (int j = 0; j < 8; j++) {
                const int col = wn * 64 + j * 8 + grp;
                float b0 = Bs[buf][kk * 8 + tig    ][col];
                float b1 = Bs[buf][kk * 8 + tig + 4][col];
                mma_tf32(acc[0][j], a[0], b0, b1);
                mma_tf32(acc[1][j], a[1], b0, b1);
            }
        }
        if (more) {
            const int nb = buf ^ 1;
            As[nb][ak + 0][ar] = f2tf(wa0.x); As[nb][ak + 1][ar] = f2tf(wa0.y);
            As[nb][ak + 2][ar] = f2tf(wa0.z); As[nb][ak + 3][ar] = f2tf(wa0.w);
            As[nb][ak + 4][ar] = f2tf(wa1.x); As[nb][ak + 5][ar] = f2tf(wa1.y);
            As[nb][ak + 6][ar] = f2tf(wa1.z); As[nb][ak + 7][ar] = f2tf(wa1.w);
            float4 c0, c1;
            c0.x = f2tf(xb0.x); c0.y = f2tf(xb0.y); c0.z = f2tf(xb0.z); c0.w = f2tf(xb0.w);
            c1.x = f2tf(xb1.x); c1.y = f2tf(xb1.y); c1.z = f2tf(xb1.z); c1.w = f2tf(xb1.w);
            *(float4*)&Bs[nb][bk][blc]     = c0;
            *(float4*)&Bs[nb][bk + 8][blc] = c1;
            __syncthreads();
        }
        buf ^= 1;
    }

    #pragma unroll
    for (int m = 0; m < 2; m++) {
        const int r0 = o0 + wm * 32 + m * 16 + grp;
        const int r1 = r0 + 8;
        const float i0 = gg[r0] * rsqrtf(vv[r0] + 1e-5f);
        const float be0 = bb[r0] - mm[r0] * i0;
        const float i1 = gg[r1] * rsqrtf(vv[r1] + 1e-5f);
        const float be1 = bb[r1] - mm[r1] * i1;
        #pragma unroll
        for (int j = 0; j < 8; j++) {
            const int l = l0 + wn * 64 + j * 8 + tig * 2;
            float2 p0, p1;
            p0.x = fmaf(acc[m][j][0], i0, be0);
            p0.y = fmaf(acc[m][j][1], i0, be0);
            p1.x = fmaf(acc[m][j][2], i1, be1);
            p1.y = fmaf(acc[m][j][3], i1, be1);
            *(float2*)&Ob[(size_t)r0 * L + l] = p0;
            *(float2*)&Ob[(size_t)r1 * L + l] = p1;
        }
    }
}

// ---------------- depthwise conv (k=3, pad=1) + BN on q channels ----------------
__global__ __launch_bounds__(256) void dwconv_bn_kernel(
    const float* __restrict__ qkv, const float* __restrict__ wdw,
    const float* __restrict__ gg, const float* __restrict__ bb,
    const float* __restrict__ mm, const float* __restrict__ vv,
    float* __restrict__ outq)
{
    int idx = blockIdx.x * blockDim.x + threadIdx.x;
    int l  = idx & (RES - 1);
    int ch = (idx >> 10) & (NHKD - 1);
    int b  = idx >> 18;
    const float* row = qkv + ((size_t)b * HQKV + ch) * RES;
    float x0 = (l > 0)       ? row[l - 1] : 0.0f;
    float x1 = row[l];
    float x2 = (l < RES - 1) ? row[l + 1] : 0.0f;
    float y = x0 * wdw[ch * 3] + x1 * wdw[ch * 3 + 1] + x2 * wdw[ch * 3 + 2];
    float inv = gg[ch] * rsqrtf(vv[ch] + 1e-5f);
    outq[idx] = (y - mm[ch]) * inv + bb[ch];
}

// ---------------- fused attention: tf32 mma + cp.async pipelines ----------------
// 512 threads (16 warps); block = (b, h, 32-row n tile).
#define NT 32
#define Q_OFF    0                        // q_s[n][36] (tf32)
#define BIAS_OFF 1152
#define DSUM_OFF 2176
#define STG_OFF  2208                     // k: 2x[32][132]=8448 ; v: 2x[128][68]=17408
#define S_OFF    (STG_OFF + 17408)        // s_s[32][1028]
#define ATTN_SMEM_FLOATS (S_OFF + 32 * 1028)
#define ATTN_SMEM_BYTES  (ATTN_SMEM_FLOATS * 4)
#define KBUF 4224                         // 32*132
#define VBUF 8704                         // 128*68

__global__ __launch_bounds__(512, 1) void attn_kernel(
    const float* __restrict__ qbuf, const float* __restrict__ qkv,
    const float* __restrict__ bias, float* __restrict__ outp)
{
    extern __shared__ __align__(16) float sh[];
    float* q_s    = sh + Q_OFF;
    float* bias_s = sh + BIAS_OFF;
    float* dsum   = sh + DSUM_OFF;
    float* stg    = sh + STG_OFF;
    float* s_s    = sh + S_OFF;
    const unsigned stg_u32 =
        (unsigned)__cvta_generic_to_shared(stg);

    const int b = blockIdx.z, h = blockIdx.y;
    const int n0 = blockIdx.x * NT;
    const int t = threadIdx.x;
    const int lane = t & 31, wrp = t >> 5;
    const int grp = lane >> 2, tig = lane & 3;

    const float* qb = qbuf + ((size_t)b * NHKD + h * KD) * RES;
    const float* kb = qkv + ((size_t)b * HQKV + NHKD + h * KD) * RES;
    const float* vb = qkv + ((size_t)b * HQKV + 2 * NHKD + h * DV) * RES;
    const float* ab = bias + h * RES;

    // stage k chunk ch (128 m cols) into buffer bf
    auto stage_k = [&](int ch, int bf) {
        #pragma unroll
        for (int r = 0; r < 2; r++) {
            int idx = t + r * 512;                 // 0..1023
            int d = idx >> 5, m4 = (idx & 31) * 4;
            unsigned dst = stg_u32 + (unsigned)(bf * KBUF + d * 132 + m4) * 4u;
            CP16(dst, kb + (size_t)d * RES + ch * 128 + m4);
        }
    };
    // stage v chunk ch (64 m cols) into buffer bf
    auto stage_v = [&](int ch, int bf) {
        #pragma unroll
        for (int r = 0; r < 4; r++) {
            int idx = t + r * 512;                 // 0..2047
            int d = idx >> 4, m4 = (idx & 15) * 4;
            unsigned dst = stg_u32 + (unsigned)(bf * VBUF + d * 68 + m4) * 4u;
            CP16(dst, vb + (size_t)d * RES + ch * 64 + m4);
        }
    };

    // kick off k chunk 0 immediately
    stage_k(0, 0);
    CP_COMMIT();

    // ---- phase 1: q tile (n-major, tf32) + bias row ----
    for (int i = t; i < 1024; i += 512) {
        int d = i >> 5, nn = i & 31;
        q_s[nn * 36 + d] = f2tf(qb[d * RES + n0 + nn]);
        bias_s[i] = ab[i];
    }
    __syncthreads();

    // ---- phase 2: S = scale*(q k) + bias via mma, 8 chunks of 128 m ----
    {
        const int nhalf = wrp & 1;
        const int msub  = wrp >> 1;
        const int nrow0 = nhalf * 16 + grp;
        const int ngA = n0 + nrow0, ngB = ngA + 8;

        float aq[4][4];
        #pragma unroll
        for (int kk = 0; kk < 4; kk++) {
            aq[kk][0] = q_s[nrow0 * 36 + kk * 8 + tig];
            aq[kk][1] = q_s[(nrow0 + 8) * 36 + kk * 8 + tig];
            aq[kk][2] = q_s[nrow0 * 36 + kk * 8 + tig + 4];
            aq[kk][3] = q_s[(nrow0 + 8) * 36 + kk * 8 + tig + 4];
        }

        for (int ch = 0; ch < 8; ch++) {
            if (ch < 7) { stage_k(ch + 1, (ch + 1) & 1); CP_COMMIT(); CP_WAIT1(); }
            else        { CP_WAIT0(); }
            __syncthreads();
            const float* ks = stg + (ch & 1) * KBUF;

            float acc2[2][4];
            #pragma unroll
            for (int j = 0; j < 2; j++)
                #pragma unroll
                for (int r = 0; r < 4; r++) acc2[j][r] = 0.0f;

            #pragma unroll
            for (int kk = 0; kk < 4; kk++) {
                #pragma unroll
                for (int j = 0; j < 2; j++) {
                    const int mc = msub * 16 + j * 8 + grp;
                    float b0 = ks[(kk * 8 + tig) * 132 + mc];
                    float b1 = ks[(kk * 8 + tig + 4) * 132 + mc];
                    mma_tf32(acc2[j], aq[kk], b0, b1);
                }
            }
            #pragma unroll
            for (int j = 0; j < 2; j++) {
                const int mg = ch * 128 + msub * 16 + j * 8 + tig * 2;
                float2 p0, p1;
                p0.x = fmaf(acc2[j][0], ATT_SCALE, bias_s[abs(ngA - mg)]);
                p0.y = fmaf(acc2[j][1], ATT_SCALE, bias_s[abs(ngA - mg - 1)]);
                p1.x = fmaf(acc2[j][2], ATT_SCALE, bias_s[abs(ngB - mg)]);
                p1.y = fmaf(acc2[j][3], ATT_SCALE, bias_s[abs(ngB - mg - 1)]);
                *(float2*)&s_s[nrow0 * 1028 + mg]       = p0;
                *(float2*)&s_s[(nrow0 + 8) * 1028 + mg] = p1;
            }
            __syncthreads();
        }
    }

    // prefetch v chunk 0 under the softmax
    stage_v(0, 0);
    CP_COMMIT();

    // ---- phase 3: softmax per row (16 warps x 2 rows) ----
    #pragma unroll
    for (int rr = 0; rr < 2; rr++) {
        int r = wrp * 2 + rr;
        float* row = s_s + r * 1028;
        float mx = -1e30f;
        for (int i = lane * 4; i < RES; i += 128) {
            float4 x = *(const float4*)&row[i];
            mx = fmaxf(mx, fmaxf(fmaxf(x.x, x.y), fmaxf(x.z, x.w)));
        }
        #pragma unroll
        for (int o = 16; o; o >>= 1) mx = fmaxf(mx, __shfl_xor_sync(0xffffffffu, mx, o));
        float sum = 0.0f;
        for (int i = lane * 4; i < RES; i += 128) {
            float4 x = *(const float4*)&row[i];
            x.x = __expf(x.x - mx); x.y = __expf(x.y - mx);
            x.z = __expf(x.z - mx); x.w = __expf(x.w - mx);
            sum += (x.x + x.y) + (x.z + x.w);
            *(float4*)&row[i] = x;
        }
        #pragma unroll
        for (int o = 16; o; o >>= 1) sum += __shfl_xor_sync(0xffffffffu, sum, o);
        if (lane == 0) dsum[r] = 1.0f / sum;
    }
    __syncthreads();

    // ---- phase 4: out[d][n] = sum_m v[d][m] p[n][m] via mma ----
    // warp tile d32 x n32, 4-way K-split; 16 chunks of 64 m.
    {
        const int dt = wrp & 3;         // d tile: dt*32
        const int ksp = wrp >> 2;       // K-split 0..3
        float c4[2][4][4];
        #pragma unroll
        for (int su = 0; su < 2; su++)
            #pragma unroll
            for (int j = 0; j < 4; j++)
                #pragma unroll
                for (int r = 0; r < 4; r++) c4[su][j][r] = 0.0f;

        for (int ch = 0; ch < 16; ch++) {
            if (ch < 15) { stage_v(ch + 1, (ch + 1) & 1); CP_COMMIT(); CP_WAIT1(); }
            else         { CP_WAIT0(); }
            __syncthreads();
            const float* vs = stg + (ch & 1) * VBUF;
            const int mbase = ch * 64;

            #pragma unroll
            for (int kk = 0; kk < 2; kk++) {
                const int k8 = ksp * 16 + kk * 8;
                float av[2][4];
                #pragma unroll
                for (int su = 0; su < 2; su++) {
                    const int dr = dt * 32 + su * 16 + grp;
                    av[su][0] = vs[dr * 68 + k8 + tig];
                    av[su][1] = vs[(dr + 8) * 68 + k8 + tig];
                    av[su][2] = vs[dr * 68 + k8 + tig + 4];
                    av[su][3] = vs[(dr + 8) * 68 + k8 + tig + 4];
                }
                #pragma unroll
                for (int j = 0; j < 4; j++) {
                    const int nrow = j * 8 + grp;
                    float b0 = s_s[nrow * 1028 + mbase + k8 + tig];
                    float b1 = s_s[nrow * 1028 + mbase + k8 + tig + 4];
                    mma_tf32(c4[0][j], av[0], b0, b1);
                    mma_tf32(c4[1][j], av[1], b0, b1);
                }
            }
            __syncthreads();
        }

        // write K-split partials to smem (reuse staging area), stride 34
        float* red = stg;
        #pragma unroll
        for (int su = 0; su < 2; su++) {
            #pragma unroll
            for (int j = 0; j < 4; j++) {
                const int d = dt * 32 + su * 16 + grp;
                const int n = j * 8 + tig * 2;
                *(float2*)&red[ksp * 4352 + d * 34 + n] =
                    make_float2(c4[su][j][0], c4[su][j][1]);
                *(float2*)&red[ksp * 4352 + (d + 8) * 34 + n] =
                    make_float2(c4[su][j][2], c4[su][j][3]);
            }
        }
        __syncthreads();

        // final reduce + /sum + relu + store
        const int d  = t >> 2;
        const int nq = (t & 3) * 8;
        float s[8];
        #pragma unroll
        for (int i = 0; i < 8; i++) s[i] = 0.0f;
        #pragma unroll
        for (int kspl = 0; kspl < 4; kspl++) {
            const float* rp = &red[kspl * 4352 + d * 34 + nq];
            #pragma unroll
            for (int i = 0; i < 4; i++) {
                float2 v = *(const float2*)&rp[i * 2];
                s[i * 2]     += v.x;
                s[i * 2 + 1] += v.y;
            }
        }
        float4 w0, w1;
        w0.x = fmaxf(s[0] * dsum[nq + 0], 0.0f);
        w0.y = fmaxf(s[1] * dsum[nq + 1], 0.0f);
        w0.z = fmaxf(s[2] * dsum[nq + 2], 0.0f);
        w0.w = fmaxf(s[3] * dsum[nq + 3], 0.0f);
        w1.x = fmaxf(s[4] * dsum[nq + 4], 0.0f);
        w1.y = fmaxf(s[5] * dsum[nq + 5], 0.0f);
        w1.z = fmaxf(s[6] * dsum[nq + 6], 0.0f);
        w1.w = fmaxf(s[7] * dsum[nq + 7], 0.0f);
        float* ob = outp + ((size_t)b * DHDIM + h * DV) * RES + n0;
        *(float4*)&ob[(size_t)d * RES + nq]     = w0;
        *(float4*)&ob[(size_t)d * RES + nq + 4] = w1;
    }
}

// --------------------------------- launch -------------------------------------
extern "C" void kernel_launch(void* const* d_in, const int* in_sizes, int n_in,
                              void* d_out, int out_size)
{
    const float* x      = (const float*)d_in[0];
    const float* w_qkv  = (const float*)d_in[1];
    const float* qkv_g  = (const float*)d_in[2];
    const float* qkv_b  = (const float*)d_in[3];
    const float* qkv_m  = (const float*)d_in[4];
    const float* qkv_v  = (const float*)d_in[5];
    const float* w_dw   = (const float*)d_in[6];
    const float* dw_g   = (const float*)d_in[7];
    const float* dw_b   = (const float*)d_in[8];
    const float* dw_m   = (const float*)d_in[9];
    const float* dw_v   = (const float*)d_in[10];
    const float* w_proj = (const float*)d_in[11];
    const float* proj_g = (const float*)d_in[12];
    const float* proj_b = (const float*)d_in[13];
    const float* proj_m = (const float*)d_in[14];
    const float* proj_v = (const float*)d_in[15];
    const float* att_bias = (const float*)d_in[16];

    float *p_qkv, *p_q, *p_att;
    cudaGetSymbolAddress((void**)&p_qkv, g_qkv);
    cudaGetSymbolAddress((void**)&p_q,   g_q);
    cudaGetSymbolAddress((void**)&p_att, g_att);

    cudaFuncSetAttribute(attn_kernel, cudaFuncAttributeMaxDynamicSharedMemorySize,
                         ATTN_SMEM_BYTES);

    gemm_tf32_bn<<<dim3(RES / 128, HQKV / 128, BATCH), 256>>>(
        w_qkv, x, qkv_g, qkv_b, qkv_m, qkv_v, p_qkv, HQKV, DIMC, RES);

    dwconv_bn_kernel<<<(BATCH * NHKD * RES) / 256, 256>>>(
        p_qkv, w_dw, dw_g, dw_b, dw_m, dw_v, p_q);

    attn_kernel<<<dim3(RES / NT, NHEAD, BATCH), 512, ATTN_SMEM_BYTES>>>(
        p_q, p_qkv, att_bias, p_att);

    gemm_tf32_bn<<<dim3(RES / 128, DIMC / 128, BATCH), 256>>>(
        w_proj, p_att, proj_g, proj_b, proj_m, proj_v, (float*)d_out,
        DIMC, DHDIM, RES);
}

// round 9
// speedup vs baseline: 3.8570x; 1.1464x over previous
#include <cuda_runtime.h>
#include <math.h>

#define BATCH 16
#define DIMC  512
#define RES   1024
#define NHKD  256
#define HQKV  1536
#define DHDIM 1024
#define NHEAD 8
#define KD    32
#define DV    128
#define ATT_SCALE 0.17677669529663687f

// ---------------- scratch (static device globals; no allocations) -------------
__device__ float g_qkv[BATCH * HQKV * RES];
__device__ float g_q  [BATCH * NHKD * RES];
__device__ float g_att[BATCH * DHDIM * RES];

// ---------------- tf32 / cp.async helpers --------------------------------------
__device__ __forceinline__ float f2tf(float x) {
    unsigned r;
    asm("cvt.rna.tf32.f32 %0, %1;" : "=r"(r) : "f"(x));
    return __uint_as_float(r);
}
__device__ __forceinline__ void mma_tf32(float c[4], const float a[4],
                                         float b0, float b1) {
    asm volatile(
        "mma.sync.aligned.m16n8k8.row.col.f32.tf32.tf32.f32 "
        "{%0,%1,%2,%3}, {%4,%5,%6,%7}, {%8,%9}, {%0,%1,%2,%3};"
        : "+f"(c[0]), "+f"(c[1]), "+f"(c[2]), "+f"(c[3])
        : "r"(__float_as_uint(a[0])), "r"(__float_as_uint(a[1])),
          "r"(__float_as_uint(a[2])), "r"(__float_as_uint(a[3])),
          "r"(__float_as_uint(b0)), "r"(__float_as_uint(b1)));
}
#define CP16(dst, src) \
    asm volatile("cp.async.cg.shared.global [%0], [%1], 16;" :: "r"(dst), "l"(src))
#define CP_COMMIT() asm volatile("cp.async.commit_group;")
#define CP_WAIT0()  asm volatile("cp.async.wait_group 0;")
#define CP_WAIT1()  asm volatile("cp.async.wait_group 1;")

// ---------------- GEMM (C[b,o,l] = sum_c W[o,c] * X[b,c,l]) + BN ---------------
// tf32 mma, 128x128 tile, K-chunk 16, 256 threads, 3-stage cp.async pipeline.
// A stage: [128 rows][20] (row-major, k contiguous), B stage: [16 k][132].
#define GSTG_A 2560                 // 128*20 floats
#define GSTG_B 2112                 // 16*132 floats
#define GSTG   (GSTG_A + GSTG_B)    // per-stage floats
#define GEMM_SMEM_BYTES (3 * GSTG * 4)

__global__ __launch_bounds__(256) void gemm_tf32_bn(
    const float* __restrict__ W, const float* __restrict__ X,
    const float* __restrict__ gg, const float* __restrict__ bb,
    const float* __restrict__ mm, const float* __restrict__ vv,
    float* __restrict__ out, int O, int C, int L)
{
    extern __shared__ __align__(16) float gsh[];
    const unsigned sh_u32 = (unsigned)__cvta_generic_to_shared(gsh);

    const int b  = blockIdx.z;
    const float* Xb = X + (size_t)b * C * L;
    float* Ob = out + (size_t)b * O * L;
    const int o0 = blockIdx.y * 128;
    const int l0 = blockIdx.x * 128;
    const int t = threadIdx.x, lane = t & 31, wid = t >> 5;
    const int wm = wid & 3, wn = wid >> 2;
    const int tig = lane & 3, grp = lane >> 2;

    float acc[2][8][4];
    #pragma unroll
    for (int m = 0; m < 2; m++)
        #pragma unroll
        for (int j = 0; j < 8; j++)
            #pragma unroll
            for (int r = 0; r < 4; r++) acc[m][j][r] = 0.0f;

    auto stage = [&](int k0, int s) {
        unsigned base = sh_u32 + (unsigned)(s * GSTG) * 4u;
        #pragma unroll
        for (int r = 0; r < 2; r++) {               // A: 128 rows x 16 k
            int idx = t + r * 256;
            int row = idx >> 2, kq = (idx & 3) * 4;
            CP16(base + (unsigned)(row * 20 + kq) * 4u,
                 &W[(size_t)(o0 + row) * C + k0 + kq]);
        }
        #pragma unroll
        for (int r = 0; r < 2; r++) {               // B: 16 k x 128 l
            int idx = t + r * 256;
            int k = idx >> 5, m4 = (idx & 31) * 4;
            CP16(base + (unsigned)(GSTG_A + k * 132 + m4) * 4u,
                 &Xb[(size_t)(k0 + k) * L + l0 + m4]);
        }
    };

    stage(0, 0); CP_COMMIT();
    stage(16, 1); CP_COMMIT();

    const int niter = C / 16;
    for (int it = 0; it < niter; it++) {
        if (it < niter - 1) { CP_WAIT1(); } else { CP_WAIT0(); }
        __syncthreads();
        if (it + 2 < niter) { stage((it + 2) * 16, (it + 2) % 3); CP_COMMIT(); }

        const float* As = gsh + (it % 3) * GSTG;
        const float* Bs = As + GSTG_A;

        #pragma unroll
        for (int kk = 0; kk < 2; kk++) {
            float a[2][4];
            #pragma unroll
            for (int m = 0; m < 2; m++) {
                const int row = wm * 32 + m * 16 + grp;
                a[m][0] = As[row * 20 + kk * 8 + tig];
                a[m][1] = As[(row + 8) * 20 + kk * 8 + tig];
                a[m][2] = As[row * 20 + kk * 8 + tig + 4];
                a[m][3] = As[(row + 8) * 20 + kk * 8 + tig + 4];
            }
            #pragma unroll
            for (int j = 0; j < 8; j++) {
                const int col = wn * 64 + j * 8 + grp;
                float b0 = Bs[(kk * 8 + tig) * 132 + col];
                float b1 = Bs[(kk * 8 + tig + 4) * 132 + col];
                mma_tf32(acc[0][j], a[0], b0, b1);
                mma_tf32(acc[1][j], a[1], b0, b1);
            }
        }
        __syncthreads();
    }

    #pragma unroll
    for (int m = 0; m < 2; m++) {
        const int r0 = o0 + wm * 32 + m * 16 + grp;
        const int r1 = r0 + 8;
        const float i0 = gg[r0] * rsqrtf(vv[r0] + 1e-5f);
        const float be0 = bb[r0] - mm[r0] * i0;
        const float i1 = gg[r1] * rsqrtf(vv[r1] + 1e-5f);
        const float be1 = bb[r1] - mm[r1] * i1;
        #pragma unroll
        for (int j = 0; j < 8; j++) {
            const int l = l0 + wn * 64 + j * 8 + tig * 2;
            float2 p0, p1;
            p0.x = fmaf(acc[m][j][0], i0, be0);
            p0.y = fmaf(acc[m][j][1], i0, be0);
            p1.x = fmaf(acc[m][j][2], i1, be1);
            p1.y = fmaf(acc[m][j][3], i1, be1);
            *(float2*)&Ob[(size_t)r0 * L + l] = p0;
            *(float2*)&Ob[(size_t)r1 * L + l] = p1;
        }
    }
}

// ---------------- depthwise conv (k=3, pad=1) + BN on q channels ----------------
__global__ __launch_bounds__(256) void dwconv_bn_kernel(
    const float* __restrict__ qkv, const float* __restrict__ wdw,
    const float* __restrict__ gg, const float* __restrict__ bb,
    const float* __restrict__ mm, const float* __restrict__ vv,
    float* __restrict__ outq)
{
    int idx = blockIdx.x * blockDim.x + threadIdx.x;
    int l  = idx & (RES - 1);
    int ch = (idx >> 10) & (NHKD - 1);
    int b  = idx >> 18;
    const float* row = qkv + ((size_t)b * HQKV + ch) * RES;
    float x0 = (l > 0)       ? row[l - 1] : 0.0f;
    float x1 = row[l];
    float x2 = (l < RES - 1) ? row[l + 1] : 0.0f;
    float y = x0 * wdw[ch * 3] + x1 * wdw[ch * 3 + 1] + x2 * wdw[ch * 3 + 2];
    float inv = gg[ch] * rsqrtf(vv[ch] + 1e-5f);
    outq[idx] = (y - mm[ch]) * inv + bb[ch];
}

// ---------------- fused attention: tf32 mma + cp.async pipelines ----------------
// 512 threads (16 warps); block = (b, h, 32-row n tile).
#define NT 32
#define Q_OFF    0                        // q_s[n][36] (tf32)
#define BIAS_OFF 1152
#define DSUM_OFF 2176
#define STG_OFF  2208                     // k: 2x[32][132]=8448 ; v: 2x[128][68]=17408
#define S_OFF    (STG_OFF + 17408)        // s_s[32][1028]
#define ATTN_SMEM_FLOATS (S_OFF + 32 * 1028)
#define ATTN_SMEM_BYTES  (ATTN_SMEM_FLOATS * 4)
#define KBUF 4224                         // 32*132
#define VBUF 8704                         // 128*68

__global__ __launch_bounds__(512, 1) void attn_kernel(
    const float* __restrict__ qbuf, const float* __restrict__ qkv,
    const float* __restrict__ bias, float* __restrict__ outp)
{
    extern __shared__ __align__(16) float sh[];
    float* q_s    = sh + Q_OFF;
    float* bias_s = sh + BIAS_OFF;
    float* dsum   = sh + DSUM_OFF;
    float* stg    = sh + STG_OFF;
    float* s_s    = sh + S_OFF;
    const unsigned stg_u32 =
        (unsigned)__cvta_generic_to_shared(stg);

    const int b = blockIdx.z, h = blockIdx.y;
    const int n0 = blockIdx.x * NT;
    const int t = threadIdx.x;
    const int lane = t & 31, wrp = t >> 5;
    const int grp = lane >> 2, tig = lane & 3;

    const float* qb = qbuf + ((size_t)b * NHKD + h * KD) * RES;
    const float* kb = qkv + ((size_t)b * HQKV + NHKD + h * KD) * RES;
    const float* vb = qkv + ((size_t)b * HQKV + 2 * NHKD + h * DV) * RES;
    const float* ab = bias + h * RES;

    auto stage_k = [&](int ch, int bf) {
        #pragma unroll
        for (int r = 0; r < 2; r++) {
            int idx = t + r * 512;
            int d = idx >> 5, m4 = (idx & 31) * 4;
            unsigned dst = stg_u32 + (unsigned)(bf * KBUF + d * 132 + m4) * 4u;
            CP16(dst, kb + (size_t)d * RES + ch * 128 + m4);
        }
    };
    auto stage_v = [&](int ch, int bf) {
        #pragma unroll
        for (int r = 0; r < 4; r++) {
            int idx = t + r * 512;
            int d = idx >> 4, m4 = (idx & 15) * 4;
            unsigned dst = stg_u32 + (unsigned)(bf * VBUF + d * 68 + m4) * 4u;
            CP16(dst, vb + (size_t)d * RES + ch * 64 + m4);
        }
    };

    stage_k(0, 0);
    CP_COMMIT();

    for (int i = t; i < 1024; i += 512) {
        int d = i >> 5, nn = i & 31;
        q_s[nn * 36 + d] = f2tf(qb[d * RES + n0 + nn]);
        bias_s[i] = ab[i];
    }
    __syncthreads();

    // ---- phase 2: S = scale*(q k) + bias via mma, 8 chunks of 128 m ----
    {
        const int nhalf = wrp & 1;
        const int msub  = wrp >> 1;
        const int nrow0 = nhalf * 16 + grp;
        const int ngA = n0 + nrow0, ngB = ngA + 8;

        float aq[4][4];
        #pragma unroll
        for (int kk = 0; kk < 4; kk++) {
            aq[kk][0] = q_s[nrow0 * 36 + kk * 8 + tig];
            aq[kk][1] = q_s[(nrow0 + 8) * 36 + kk * 8 + tig];
            aq[kk][2] = q_s[nrow0 * 36 + kk * 8 + tig + 4];
            aq[kk][3] = q_s[(nrow0 + 8) * 36 + kk * 8 + tig + 4];
        }

        for (int ch = 0; ch < 8; ch++) {
            if (ch < 7) { stage_k(ch + 1, (ch + 1) & 1); CP_COMMIT(); CP_WAIT1(); }
            else        { CP_WAIT0(); }
            __syncthreads();
            const float* ks = stg + (ch & 1) * KBUF;

            float acc2[2][4];
            #pragma unroll
            for (int j = 0; j < 2; j++)
                #pragma unroll
                for (int r = 0; r < 4; r++) acc2[j][r] = 0.0f;

            #pragma unroll
            for (int kk = 0; kk < 4; kk++) {
                #pragma unroll
                for (int j = 0; j < 2; j++) {
                    const int mc = msub * 16 + j * 8 + grp;
                    float b0 = ks[(kk * 8 + tig) * 132 + mc];
                    float b1 = ks[(kk * 8 + tig + 4) * 132 + mc];
                    mma_tf32(acc2[j], aq[kk], b0, b1);
                }
            }
            #pragma unroll
            for (int j = 0; j < 2; j++) {
                const int mg = ch * 128 + msub * 16 + j * 8 + tig * 2;
                float2 p0, p1;
                p0.x = fmaf(acc2[j][0], ATT_SCALE, bias_s[abs(ngA - mg)]);
                p0.y = fmaf(acc2[j][1], ATT_SCALE, bias_s[abs(ngA - mg - 1)]);
                p1.x = fmaf(acc2[j][2], ATT_SCALE, bias_s[abs(ngB - mg)]);
                p1.y = fmaf(acc2[j][3], ATT_SCALE, bias_s[abs(ngB - mg - 1)]);
                *(float2*)&s_s[nrow0 * 1028 + mg]       = p0;
                *(float2*)&s_s[(nrow0 + 8) * 1028 + mg] = p1;
            }
            __syncthreads();
        }
    }

    stage_v(0, 0);
    CP_COMMIT();

    // ---- phase 3: softmax per row (16 warps x 2 rows) ----
    #pragma unroll
    for (int rr = 0; rr < 2; rr++) {
        int r = wrp * 2 + rr;
        float* row = s_s + r * 1028;
        float mx = -1e30f;
        for (int i = lane * 4; i < RES; i += 128) {
            float4 x = *(const float4*)&row[i];
            mx = fmaxf(mx, fmaxf(fmaxf(x.x, x.y), fmaxf(x.z, x.w)));
        }
        #pragma unroll
        for (int o = 16; o; o >>= 1) mx = fmaxf(mx, __shfl_xor_sync(0xffffffffu, mx, o));
        float sum = 0.0f;
        for (int i = lane * 4; i < RES; i += 128) {
            float4 x = *(const float4*)&row[i];
            x.x = __expf(x.x - mx); x.y = __expf(x.y - mx);
            x.z = __expf(x.z - mx); x.w = __expf(x.w - mx);
            sum += (x.x + x.y) + (x.z + x.w);
            *(float4*)&row[i] = x;
        }
        #pragma unroll
        for (int o = 16; o; o >>= 1) sum += __shfl_xor_sync(0xffffffffu, sum, o);
        if (lane == 0) dsum[r] = 1.0f / sum;
    }
    __syncthreads();

    // ---- phase 4: out[d][n] = sum_m v[d][m] p[n][m] via mma ----
    {
        const int dt = wrp & 3;
        const int ksp = wrp >> 2;
        float c4[2][4][4];
        #pragma unroll
        for (int su = 0; su < 2; su++)
            #pragma unroll
            for (int j = 0; j < 4; j++)
                #pragma unroll
                for (int r = 0; r < 4; r++) c4[su][j][r] = 0.0f;

        for (int ch = 0; ch < 16; ch++) {
            if (ch < 15) { stage_v(ch + 1, (ch + 1) & 1); CP_COMMIT(); CP_WAIT1(); }
            else         { CP_WAIT0(); }
            __syncthreads();
            const float* vs = stg + (ch & 1) * VBUF;
            const int mbase = ch * 64;

            #pragma unroll
            for (int kk = 0; kk < 2; kk++) {
                const int k8 = ksp * 16 + kk * 8;
                float av[2][4];
                #pragma unroll
                for (int su = 0; su < 2; su++) {
                    const int dr = dt * 32 + su * 16 + grp;
                    av[su][0] = vs[dr * 68 + k8 + tig];
                    av[su][1] = vs[(dr + 8) * 68 + k8 + tig];
                    av[su][2] = vs[dr * 68 + k8 + tig + 4];
                    av[su][3] = vs[(dr + 8) * 68 + k8 + tig + 4];
                }
                #pragma unroll
                for (int j = 0; j < 4; j++) {
                    const int nrow = j * 8 + grp;
                    float b0 = s_s[nrow * 1028 + mbase + k8 + tig];
                    float b1 = s_s[nrow * 1028 + mbase + k8 + tig + 4];
                    mma_tf32(c4[0][j], av[0], b0, b1);
                    mma_tf32(c4[1][j], av[1], b0, b1);
                }
            }
            __syncthreads();
        }

        float* red = stg;
        #pragma unroll
        for (int su = 0; su < 2; su++) {
            #pragma unroll
            for (int j = 0; j < 4; j++) {
                const int d = dt * 32 + su * 16 + grp;
                const int n = j * 8 + tig * 2;
                *(float2*)&red[ksp * 4352 + d * 34 + n] =
                    make_float2(c4[su][j][0], c4[su][j][1]);
                *(float2*)&red[ksp * 4352 + (d + 8) * 34 + n] =
                    make_float2(c4[su][j][2], c4[su][j][3]);
            }
        }
        __syncthreads();

        const int d  = t >> 2;
        const int nq = (t & 3) * 8;
        float s[8];
        #pragma unroll
        for (int i = 0; i < 8; i++) s[i] = 0.0f;
        #pragma unroll
        for (int kspl = 0; kspl < 4; kspl++) {
            const float* rp = &red[kspl * 4352 + d * 34 + nq];
            #pragma unroll
            for (int i = 0; i < 4; i++) {
                float2 v = *(const float2*)&rp[i * 2];
                s[i * 2]     += v.x;
                s[i * 2 + 1] += v.y;
            }
        }
        float4 w0, w1;
        w0.x = fmaxf(s[0] * dsum[nq + 0], 0.0f);
        w0.y = fmaxf(s[1] * dsum[nq + 1], 0.0f);
        w0.z = fmaxf(s[2] * dsum[nq + 2], 0.0f);
        w0.w = fmaxf(s[3] * dsum[nq + 3], 0.0f);
        w1.x = fmaxf(s[4] * dsum[nq + 4], 0.0f);
        w1.y = fmaxf(s[5] * dsum[nq + 5], 0.0f);
        w1.z = fmaxf(s[6] * dsum[nq + 6], 0.0f);
        w1.w = fmaxf(s[7] * dsum[nq + 7], 0.0f);
        float* ob = outp + ((size_t)b * DHDIM + h * DV) * RES + n0;
        *(float4*)&ob[(size_t)d * RES + nq]     = w0;
        *(float4*)&ob[(size_t)d * RES + nq + 4] = w1;
    }
}

// --------------------------------- launch -------------------------------------
extern "C" void kernel_launch(void* const* d_in, const int* in_sizes, int n_in,
                              void* d_out, int out_size)
{
    const float* x      = (const float*)d_in[0];
    const float* w_qkv  = (const float*)d_in[1];
    const float* qkv_g  = (const float*)d_in[2];
    const float* qkv_b  = (const float*)d_in[3];
    const float* qkv_m  = (const float*)d_in[4];
    const float* qkv_v  = (const float*)d_in[5];
    const float* w_dw   = (const float*)d_in[6];
    const float* dw_g   = (const float*)d_in[7];
    const float* dw_b   = (const float*)d_in[8];
    const float* dw_m   = (const float*)d_in[9];
    const float* dw_v   = (const float*)d_in[10];
    const float* w_proj = (const float*)d_in[11];
    const float* proj_g = (const float*)d_in[12];
    const float* proj_b = (const float*)d_in[13];
    const float* proj_m = (const float*)d_in[14];
    const float* proj_v = (const float*)d_in[15];
    const float* att_bias = (const float*)d_in[16];

    float *p_qkv, *p_q, *p_att;
    cudaGetSymbolAddress((void**)&p_qkv, g_qkv);
    cudaGetSymbolAddress((void**)&p_q,   g_q);
    cudaGetSymbolAddress((void**)&p_att, g_att);

    cudaFuncSetAttribute(gemm_tf32_bn, cudaFuncAttributeMaxDynamicSharedMemorySize,
                         GEMM_SMEM_BYTES);
    cudaFuncSetAttribute(attn_kernel, cudaFuncAttributeMaxDynamicSharedMemorySize,
                         ATTN_SMEM_BYTES);

    gemm_tf32_bn<<<dim3(RES / 128, HQKV / 128, BATCH), 256, GEMM_SMEM_BYTES>>>(
        w_qkv, x, qkv_g, qkv_b, qkv_m, qkv_v, p_qkv, HQKV, DIMC, RES);

    dwconv_bn_kernel<<<(BATCH * NHKD * RES) / 256, 256>>>(
        p_qkv, w_dw, dw_g, dw_b, dw_m, dw_v, p_q);

    attn_kernel<<<dim3(RES / NT, NHEAD, BATCH), 512, ATTN_SMEM_BYTES>>>(
        p_q, p_qkv, att_bias, p_att);

    gemm_tf32_bn<<<dim3(RES / 128, DIMC / 128, BATCH), 256, GEMM_SMEM_BYTES>>>(
        w_proj, p_att, proj_g, proj_b, proj_m, proj_v, (float*)d_out,
        DIMC, DHDIM, RES);
}